// round 9
// baseline (speedup 1.0000x reference)
#include <cuda_runtime.h>
#include <cuda_fp16.h>
#include <cstdint>

#define TT 512
#define BB 128
#define HH 512
#define LL 6
#define CC 60
#define J3 75
#define K0P 128
#define BH (BB*HH)
#define MM (TT*BB)
#define NN 512
#define EPSBN 1e-5f

// fused layer kernel tiling: per CTA: one b, 128 h-cols, 4 t-chunks of 128
#define BM 128
#define BN 128
#define BK 32
#define GT 256
#define NSTAGE 3
#define STAGE_BYTES 24576   // A(8K)+B1(8K)+B2(8K)
#define OFF_SA  0
#define OFF_SB1 8192
#define OFF_SB2 16384
#define SCAN_STRIDE 136     // floats per row (bank-shift 8)
#define FSMEM (NSTAGE*STAGE_BYTES)   // 73728 >= 128*136*4 = 69632 (scanbuf overlays stages)

// activations stored b-major: A[(b*TT + t)*K + k]
__device__ __half g_Aping[(size_t)MM * HH];
__device__ __half g_Apong[(size_t)MM * HH];
__device__ __half g_B1[HH * HH];
__device__ __half g_B2[HH * HH];
__device__ float g_beff[HH];
__device__ float g_scale[HH];
__device__ float g_shift[HH];
__device__ float g_sum[LL * HH];
__device__ float g_sumsq[LL * HH];
__device__ float g_hlast[BH];
__device__ float g_probe;

__device__ __forceinline__ uint32_t smem_u32(const void* p) {
    uint32_t a;
    asm("{ .reg .u64 t; cvta.to.shared.u64 t, %1; cvt.u32.u64 %0, t; }" : "=r"(a) : "l"(p));
    return a;
}
__device__ __forceinline__ uint32_t swz64(uint32_t off) { return off ^ ((off >> 3) & 0x30); }
__device__ __forceinline__ void cp16(uint32_t dst, const void* src) {
    asm volatile("cp.async.cg.shared.global [%0], [%1], 16;\n" :: "r"(dst), "l"(src));
}
__device__ __forceinline__ void cp_commit() { asm volatile("cp.async.commit_group;\n" ::: "memory"); }
template <int N> __device__ __forceinline__ void cp_wait() {
    asm volatile("cp.async.wait_group %0;\n" :: "n"(N) : "memory");
}
__device__ __forceinline__ void ldm_x4(uint32_t& r0, uint32_t& r1, uint32_t& r2, uint32_t& r3,
                                       uint32_t addr) {
    asm volatile("ldmatrix.sync.aligned.m8n8.x4.shared.b16 {%0,%1,%2,%3}, [%4];"
        : "=r"(r0), "=r"(r1), "=r"(r2), "=r"(r3) : "r"(addr));
}
__device__ __forceinline__ void mma_f16(float* c, const uint32_t* a, uint32_t b0, uint32_t b1) {
    asm volatile("mma.sync.aligned.m16n8k16.row.col.f32.f16.f16.f32 "
        "{%0,%1,%2,%3}, {%4,%5,%6,%7}, {%8,%9}, {%0,%1,%2,%3};"
        : "+f"(c[0]), "+f"(c[1]), "+f"(c[2]), "+f"(c[3])
        : "r"(a[0]), "r"(a[1]), "r"(a[2]), "r"(a[3]), "r"(b0), "r"(b1));
}
__device__ __forceinline__ void hsplit(float v, __half& h1, __half& h2) {
    h1 = __float2half_rn(v);
    h2 = __float2half_rn(v - __half2float(h1));
}

__global__ void zero_stats_kernel() {
    int i = blockIdx.x * blockDim.x + threadIdx.x;
    if (i < LL * HH) { g_sum[i] = 0.f; g_sumsq[i] = 0.f; }
}

__global__ void probe_kernel() { g_probe = 1.f; }

// x [T,B,75] -> A0 b-major [(b*TT+t)*128 + k]
__global__ void pad_x_kernel(const float* __restrict__ x) {
    int idx = blockIdx.x * blockDim.x + threadIdx.x;
    if (idx >= MM * K0P) return;
    int k = idx & 127;
    int bt = idx >> 7;          // b*TT + t
    int b = bt >> 9, t = bt & (TT - 1);
    float v = (k < J3) ? x[(size_t)(t * BB + b) * J3 + k] : 0.f;
    g_Aping[idx] = __float2half_rn(v);
}

__global__ void prep_w0_kernel(const float* __restrict__ W0, const float* __restrict__ b0) {
    int idx = blockIdx.x * blockDim.x + threadIdx.x;
    if (idx < HH * K0P) {
        int n = idx >> 7, k = idx & 127;
        float v = (k < J3) ? W0[n * J3 + k] : 0.f;
        __half h1, h2; hsplit(v, h1, h2);
        g_B1[idx] = h1; g_B2[idx] = h2;
    }
    if (idx < HH) g_beff[idx] = b0[idx];
}

__global__ void scale_shift_kernel(const float* __restrict__ sum,
                                   const float* __restrict__ sumsq,
                                   const float* __restrict__ gamma,
                                   const float* __restrict__ beta) {
    int h = blockIdx.x * blockDim.x + threadIdx.x;
    if (h >= HH) return;
    const float inv = 1.0f / (float)(TT * BB);
    float mean = sum[h] * inv;
    float var  = sumsq[h] * inv - mean * mean;
    float sc   = gamma[h] * rsqrtf(var + EPSBN);
    g_scale[h] = sc;
    g_shift[h] = beta[h] - mean * sc;
}

// one block per output row h: BN affine in smem, fold into W row + bias (shuffle reduce)
__global__ __launch_bounds__(HH) void fold_all_kernel(
    const float* __restrict__ W, const float* __restrict__ bh,
    const float* __restrict__ sum, const float* __restrict__ sumsq,
    const float* __restrict__ gamma, const float* __restrict__ beta) {
    __shared__ float s_scale[HH], s_shift[HH], s_warp[16];
    const int t = threadIdx.x;
    {
        const float inv = 1.0f / (float)(TT * BB);
        float mean = sum[t] * inv;
        float var  = sumsq[t] * inv - mean * mean;
        float sc   = gamma[t] * rsqrtf(var + EPSBN);
        s_scale[t] = sc;
        s_shift[t] = beta[t] - mean * sc;
    }
    __syncthreads();
    const int h = blockIdx.x;
    float w = W[h * HH + t];
    float v = w * s_scale[t];
    __half h1, h2; hsplit(v, h1, h2);
    g_B1[h * HH + t] = h1;
    g_B2[h * HH + t] = h2;
    float r = w * s_shift[t];
#pragma unroll
    for (int o = 16; o > 0; o >>= 1) r += __shfl_down_sync(0xFFFFFFFFu, r, o);
    if ((t & 31) == 0) s_warp[t >> 5] = r;
    __syncthreads();
    if (t < 32) {
        float x2 = (t < 16) ? s_warp[t] : 0.f;
#pragma unroll
        for (int o = 8; o > 0; o >>= 1) x2 += __shfl_down_sync(0xFFFFFFFFu, x2, o);
        if (t == 0) g_beff[h] = bh[h] + x2;
    }
}

// Fused layer: per CTA (n-tile, b): for 4 t-chunks: GEMM 128x128 -> smem -> scan
// A is b-major: row (b*TT + t) has K contiguous elements
template <bool WRITE_NEXT>
__global__ __launch_bounds__(GT, 2) void layer_fused(
    const __half* __restrict__ A,
    const __half* __restrict__ B1, const __half* __restrict__ B2,
    const float* __restrict__ bias, const float* __restrict__ u,
    __half* __restrict__ Anext, float* __restrict__ hlast,
    float* __restrict__ gsum, float* __restrict__ gsumsq, int K) {
    extern __shared__ __align__(128) char smem[];
    const uint32_t sb = smem_u32(smem);
    float* scanbuf = (float*)smem;                    // overlays pipeline stages
    const int tid = threadIdx.x, wid = tid >> 5, lane = tid & 31;
    const int n0 = blockIdx.x * BN;
    const int b  = blockIdx.y;
    const int NC = K / BK;
    const int wm = wid & 1;
    const int wn = wid >> 1;
    const __half* Ab = A + (size_t)b * TT * K;        // contiguous [TT x K] block

    float s_state = 0.f, l_sum = 0.f, l_sq = 0.f, uu = 0.f, bb = 0.f;
    if (tid < 128) { uu = u[n0 + tid]; bb = bias[n0 + tid]; }

    for (int tc = 0; tc < 4; tc++) {
        float acc[4][4][4];
#pragma unroll
        for (int i = 0; i < 4; i++)
#pragma unroll
            for (int j = 0; j < 4; j++)
#pragma unroll
                for (int q = 0; q < 4; q++) acc[i][j][q] = 0.f;

        auto load_stage = [&](int c, int st_i) {
            const uint32_t st = sb + st_i * STAGE_BYTES;
            const int k0 = c * BK;
#pragma unroll
            for (int i = 0; i < 6; i++) {
                int g = i * GT + tid;
                int arr = g >> 9;                // 0:A 1:B1 2:B2
                int rem = g & 511;
                int row = rem >> 2, ch = rem & 3;
                const __half* src;
                if (arr == 0)      src = Ab + ((size_t)(tc * 128 + row) * K + k0 + ch * 8);
                else if (arr == 1) src = B1 + ((size_t)(n0 + row) * K + k0 + ch * 8);
                else               src = B2 + ((size_t)(n0 + row) * K + k0 + ch * 8);
                cp16(st + arr * 8192 + swz64((uint32_t)(row * 64 + ch * 16)), src);
            }
            cp_commit();
        };

        load_stage(0, 0);
        load_stage(1, 1);

        for (int c = 0; c < NC; c++) {
            cp_wait<1>();
            __syncthreads();
            if (c + 2 < NC) load_stage(c + 2, (c + 2) % NSTAGE);
            else cp_commit();

            const uint32_t st = sb + (c % NSTAGE) * STAGE_BYTES;
#pragma unroll
            for (int ks = 0; ks < 2; ks++) {
                const uint32_t cb = ks * 32 + (lane >> 4) * 16;
                uint32_t af[4][4];
#pragma unroll
                for (int mi = 0; mi < 4; mi++) {
                    uint32_t row = wm * 64 + mi * 16 + (lane & 15);
                    uint32_t off = swz64(row * 64 + cb);
                    ldm_x4(af[mi][0], af[mi][1], af[mi][2], af[mi][3], st + OFF_SA + off);
                }
                uint32_t b1f[4][2], b2f[4][2];
#pragma unroll
                for (int ni = 0; ni < 2; ni++) {
                    uint32_t row = wn * 32 + ni * 16 + (lane & 15);
                    uint32_t off = swz64(row * 64 + cb);
                    uint32_t r0, r1, r2, r3;
                    ldm_x4(r0, r1, r2, r3, st + OFF_SB1 + off);
                    b1f[2*ni][0] = r0; b1f[2*ni][1] = r2;
                    b1f[2*ni+1][0] = r1; b1f[2*ni+1][1] = r3;
                    ldm_x4(r0, r1, r2, r3, st + OFF_SB2 + off);
                    b2f[2*ni][0] = r0; b2f[2*ni][1] = r2;
                    b2f[2*ni+1][0] = r1; b2f[2*ni+1][1] = r3;
                }
#pragma unroll
                for (int mi = 0; mi < 4; mi++)
#pragma unroll
                    for (int nf = 0; nf < 4; nf++)
                        mma_f16(acc[mi][nf], af[mi], b1f[nf][0], b1f[nf][1]);
#pragma unroll
                for (int mi = 0; mi < 4; mi++)
#pragma unroll
                    for (int nf = 0; nf < 4; nf++)
                        mma_f16(acc[mi][nf], af[mi], b2f[nf][0], b2f[nf][1]);
            }
            __syncthreads();
        }

        cp_wait<0>();
        __syncthreads();

        // dump accumulators: scanbuf[t_local][h_local]
        {
            const int group = lane >> 2, tid4 = lane & 3;
#pragma unroll
            for (int nf = 0; nf < 4; nf++) {
                int hc = wn * 32 + nf * 8 + tid4 * 2;
#pragma unroll
                for (int mi = 0; mi < 4; mi++) {
                    int tr = wm * 64 + mi * 16 + group;
                    float2 v0 = { acc[mi][nf][0], acc[mi][nf][1] };
                    float2 v1 = { acc[mi][nf][2], acc[mi][nf][3] };
                    *(float2*)&scanbuf[tr * SCAN_STRIDE + hc] = v0;
                    *(float2*)&scanbuf[(tr + 8) * SCAN_STRIDE + hc] = v1;
                }
            }
        }
        __syncthreads();

        // scan this chunk: threads 0..127, one h-col each; writes b-major
        if (tid < 128) {
#pragma unroll 1
            for (int t0 = 0; t0 < 128; t0 += 8) {
                float v[8];
#pragma unroll
                for (int j = 0; j < 8; j++)
                    v[j] = scanbuf[(t0 + j) * SCAN_STRIDE + tid];
#pragma unroll
                for (int j = 0; j < 8; j++) {
                    float y = v[j] + bb;
                    s_state = fmaxf(fmaf(uu, s_state, y), 0.f);
                    if (WRITE_NEXT) {
                        size_t m = (size_t)b * TT + (tc * 128 + t0 + j);
                        Anext[m * HH + n0 + tid] = __float2half_rn(s_state);
                    }
                    l_sum += s_state;
                    l_sq = fmaf(s_state, s_state, l_sq);
                }
            }
        }
        __syncthreads();
    }

    if (tid < 128) {
        if (!WRITE_NEXT) hlast[(size_t)b * HH + n0 + tid] = s_state;
        atomicAdd(&gsum[n0 + tid], l_sum);
        atomicAdd(&gsumsq[n0 + tid], l_sq);
    }
}

__global__ void final_kernel(const float* __restrict__ hl,
                             const float* __restrict__ Wout,
                             const float* __restrict__ bout,
                             float* __restrict__ out) {
    __shared__ float sh[HH];
    int b = blockIdx.x;
    for (int h = threadIdx.x; h < HH; h += blockDim.x)
        sh[h] = fmaf(hl[b * HH + h], g_scale[h], g_shift[h]);
    __syncthreads();
    int c = threadIdx.x;
    if (c < CC) {
        float acc = bout[c];
#pragma unroll 8
        for (int h = 0; h < HH; h++)
            acc = fmaf(sh[h], Wout[c * HH + h], acc);
        out[b * CC + c] = acc;
    }
}

extern "C" void kernel_launch(void* const* d_in, const int* in_sizes, int n_in,
                              void* d_out, int out_size) {
    const float* x     = (const float*)d_in[0];
    const float* W0    = (const float*)d_in[1];
    const float* b0    = (const float*)d_in[2];
    const float* Wh    = (const float*)d_in[3];
    const float* bh    = (const float*)d_in[4];
    const float* u     = (const float*)d_in[5];
    const float* gamma = (const float*)d_in[6];
    const float* beta  = (const float*)d_in[7];
    const float* Wout  = (const float*)d_in[8];
    const float* bout  = (const float*)d_in[9];
    float* out = (float*)d_out;

    float *beff, *sum, *sumsq, *hlast;
    __half *Aping, *Apong, *B1, *B2;
    cudaGetSymbolAddress((void**)&Aping, g_Aping);
    cudaGetSymbolAddress((void**)&Apong, g_Apong);
    cudaGetSymbolAddress((void**)&B1, g_B1);
    cudaGetSymbolAddress((void**)&B2, g_B2);
    cudaGetSymbolAddress((void**)&beff, g_beff);
    cudaGetSymbolAddress((void**)&sum, g_sum);
    cudaGetSymbolAddress((void**)&sumsq, g_sumsq);
    cudaGetSymbolAddress((void**)&hlast, g_hlast);

    cudaFuncSetAttribute(layer_fused<true>, cudaFuncAttributeMaxDynamicSharedMemorySize, FSMEM);
    cudaFuncSetAttribute(layer_fused<false>, cudaFuncAttributeMaxDynamicSharedMemorySize, FSMEM);

    // launch order tuned so ncu (-s 5) captures fold_all for layer 1:
    // 0:zero 1:pad 2:prep 3:probe 4:layer0 5:fold_all ...
    zero_stats_kernel<<<(LL * HH + 255) / 256, 256>>>();
    pad_x_kernel<<<(MM * K0P + 255) / 256, 256>>>(x);
    prep_w0_kernel<<<(HH * K0P + 255) / 256, 256>>>(W0, b0);
    probe_kernel<<<1, 1>>>();

    dim3 fgrid(NN / BN, BB);

    layer_fused<true><<<fgrid, GT, FSMEM>>>(Aping, B1, B2, beff, u, Apong,
                                            nullptr, sum, sumsq, K0P);
    __half* cur = Apong;
    __half* nxt = Aping;

    for (int l = 1; l < LL; l++) {
        const float* Wl  = Wh + (size_t)(l - 1) * HH * HH;
        const float* bhl = bh + (size_t)(l - 1) * HH;
        fold_all_kernel<<<HH, HH>>>(Wl, bhl, sum + (l - 1) * HH, sumsq + (l - 1) * HH,
                                    gamma + (l - 1) * HH, beta + (l - 1) * HH);
        if (l < LL - 1) {
            layer_fused<true><<<fgrid, GT, FSMEM>>>(cur, B1, B2, beff, u + l * HH, nxt,
                                                    nullptr, sum + l * HH, sumsq + l * HH, HH);
            __half* t = cur; cur = nxt; nxt = t;
        } else {
            layer_fused<false><<<fgrid, GT, FSMEM>>>(cur, B1, B2, beff, u + l * HH, nullptr,
                                                     hlast, sum + l * HH, sumsq + l * HH, HH);
        }
    }

    scale_shift_kernel<<<2, 256>>>(sum + (LL - 1) * HH, sumsq + (LL - 1) * HH,
                                   gamma + (LL - 1) * HH, beta + (LL - 1) * HH);
    final_kernel<<<BB, 64>>>(hlast, Wout, bout, out);
}

// round 10
// speedup vs baseline: 1.0678x; 1.0678x over previous
#include <cuda_runtime.h>
#include <cuda_fp16.h>
#include <cstdint>

#define TT 512
#define BB 128
#define HH 512
#define LL 6
#define CC 60
#define J3 75
#define K0P 128
#define BH (BB*HH)
#define MM (TT*BB)
#define NN 512
#define EPSBN 1e-5f

// fused layer kernel tiling: per CTA: one b, 128 h-cols, 4 t-chunks of 128
#define BM 128
#define BN 128
#define BK 32
#define GT 256
#define NSTAGE 4
#define STAGE_BYTES 24576   // A(8K)+B1(8K)+B2(8K)
#define OFF_SA  0
#define OFF_SB1 8192
#define OFF_SB2 16384
#define SCAN_STRIDE 136     // floats per row (bank-shift 8)
#define FSMEM (NSTAGE*STAGE_BYTES)   // 98304; scanbuf (69632) overlays stages 0-2

// activations stored b-major: A[(b*TT + t)*K + k]
__device__ __half g_Aping[(size_t)MM * HH];
__device__ __half g_Apong[(size_t)MM * HH];
__device__ __half g_B1[HH * HH];
__device__ __half g_B2[HH * HH];
__device__ float g_beff[HH];
__device__ float g_scale[HH];
__device__ float g_shift[HH];
__device__ float g_sum[LL * HH];
__device__ float g_sumsq[LL * HH];
__device__ float g_hlast[BH];

__device__ __forceinline__ uint32_t smem_u32(const void* p) {
    uint32_t a;
    asm("{ .reg .u64 t; cvta.to.shared.u64 t, %1; cvt.u32.u64 %0, t; }" : "=r"(a) : "l"(p));
    return a;
}
__device__ __forceinline__ uint32_t swz64(uint32_t off) { return off ^ ((off >> 3) & 0x30); }
__device__ __forceinline__ void cp16(uint32_t dst, const void* src) {
    asm volatile("cp.async.cg.shared.global [%0], [%1], 16;\n" :: "r"(dst), "l"(src));
}
__device__ __forceinline__ void cp_commit() { asm volatile("cp.async.commit_group;\n" ::: "memory"); }
template <int N> __device__ __forceinline__ void cp_wait() {
    asm volatile("cp.async.wait_group %0;\n" :: "n"(N) : "memory");
}
__device__ __forceinline__ void ldm_x4(uint32_t& r0, uint32_t& r1, uint32_t& r2, uint32_t& r3,
                                       uint32_t addr) {
    asm volatile("ldmatrix.sync.aligned.m8n8.x4.shared.b16 {%0,%1,%2,%3}, [%4];"
        : "=r"(r0), "=r"(r1), "=r"(r2), "=r"(r3) : "r"(addr));
}
__device__ __forceinline__ void mma_f16(float* c, const uint32_t* a, uint32_t b0, uint32_t b1) {
    asm volatile("mma.sync.aligned.m16n8k16.row.col.f32.f16.f16.f32 "
        "{%0,%1,%2,%3}, {%4,%5,%6,%7}, {%8,%9}, {%0,%1,%2,%3};"
        : "+f"(c[0]), "+f"(c[1]), "+f"(c[2]), "+f"(c[3])
        : "r"(a[0]), "r"(a[1]), "r"(a[2]), "r"(a[3]), "r"(b0), "r"(b1));
}
__device__ __forceinline__ void hsplit(float v, __half& h1, __half& h2) {
    h1 = __float2half_rn(v);
    h2 = __float2half_rn(v - __half2float(h1));
}

// merged prep: zero stats + pad x (b-major) + split W0 + copy b0
__global__ void prep_all_kernel(const float* __restrict__ x,
                                const float* __restrict__ W0,
                                const float* __restrict__ b0) {
    int idx = blockIdx.x * blockDim.x + threadIdx.x;
    if (idx < LL * HH) { g_sum[idx] = 0.f; g_sumsq[idx] = 0.f; }
    if (idx < HH) g_beff[idx] = b0[idx];
    if (idx < HH * K0P) {
        int n = idx >> 7, k = idx & 127;
        float v = (k < J3) ? W0[n * J3 + k] : 0.f;
        __half h1, h2; hsplit(v, h1, h2);
        g_B1[idx] = h1; g_B2[idx] = h2;
    }
    if (idx < MM * K0P) {
        int k = idx & 127;
        int bt = idx >> 7;          // b*TT + t
        int b = bt >> 9, t = bt & (TT - 1);
        float v = (k < J3) ? x[(size_t)(t * BB + b) * J3 + k] : 0.f;
        g_Aping[idx] = __float2half_rn(v);
    }
}

__global__ void scale_shift_kernel(const float* __restrict__ sum,
                                   const float* __restrict__ sumsq,
                                   const float* __restrict__ gamma,
                                   const float* __restrict__ beta) {
    int h = blockIdx.x * blockDim.x + threadIdx.x;
    if (h >= HH) return;
    const float inv = 1.0f / (float)(TT * BB);
    float mean = sum[h] * inv;
    float var  = sumsq[h] * inv - mean * mean;
    float sc   = gamma[h] * rsqrtf(var + EPSBN);
    g_scale[h] = sc;
    g_shift[h] = beta[h] - mean * sc;
}

// one block per output row h: BN affine in smem, fold into W row + bias (shuffle reduce)
__global__ __launch_bounds__(HH) void fold_all_kernel(
    const float* __restrict__ W, const float* __restrict__ bh,
    const float* __restrict__ sum, const float* __restrict__ sumsq,
    const float* __restrict__ gamma, const float* __restrict__ beta) {
    __shared__ float s_scale[HH], s_shift[HH], s_warp[16];
    const int t = threadIdx.x;
    {
        const float inv = 1.0f / (float)(TT * BB);
        float mean = sum[t] * inv;
        float var  = sumsq[t] * inv - mean * mean;
        float sc   = gamma[t] * rsqrtf(var + EPSBN);
        s_scale[t] = sc;
        s_shift[t] = beta[t] - mean * sc;
    }
    __syncthreads();
    const int h = blockIdx.x;
    float w = W[h * HH + t];
    float v = w * s_scale[t];
    __half h1, h2; hsplit(v, h1, h2);
    g_B1[h * HH + t] = h1;
    g_B2[h * HH + t] = h2;
    float r = w * s_shift[t];
#pragma unroll
    for (int o = 16; o > 0; o >>= 1) r += __shfl_down_sync(0xFFFFFFFFu, r, o);
    if ((t & 31) == 0) s_warp[t >> 5] = r;
    __syncthreads();
    if (t < 32) {
        float x2 = (t < 16) ? s_warp[t] : 0.f;
#pragma unroll
        for (int o = 8; o > 0; o >>= 1) x2 += __shfl_down_sync(0xFFFFFFFFu, x2, o);
        if (t == 0) g_beff[h] = bh[h] + x2;
    }
}

// Fused layer: per CTA (n-tile, b): for 4 t-chunks: GEMM 128x128 -> smem -> scan
// A is b-major: row (b*TT + t) has K contiguous elements
// Pipeline: 4 stages, prefetch depth 3, ONE barrier per k-iteration.
template <bool WRITE_NEXT>
__global__ __launch_bounds__(GT, 2) void layer_fused(
    const __half* __restrict__ A,
    const __half* __restrict__ B1, const __half* __restrict__ B2,
    const float* __restrict__ bias, const float* __restrict__ u,
    __half* __restrict__ Anext, float* __restrict__ hlast,
    float* __restrict__ gsum, float* __restrict__ gsumsq, int K) {
    extern __shared__ __align__(128) char smem[];
    const uint32_t sb = smem_u32(smem);
    float* scanbuf = (float*)smem;                    // overlays stages 0-2
    const int tid = threadIdx.x, wid = tid >> 5, lane = tid & 31;
    const int n0 = blockIdx.x * BN;
    const int b  = blockIdx.y;
    const int NC = K / BK;
    const int wm = wid & 1;
    const int wn = wid >> 1;
    const __half* Ab = A + (size_t)b * TT * K;        // contiguous [TT x K] block

    float s_state = 0.f, l_sum = 0.f, l_sq = 0.f, uu = 0.f, bb = 0.f;
    if (tid < 128) { uu = u[n0 + tid]; bb = bias[n0 + tid]; }

    for (int tc = 0; tc < 4; tc++) {
        float acc[4][4][4];
#pragma unroll
        for (int i = 0; i < 4; i++)
#pragma unroll
            for (int j = 0; j < 4; j++)
#pragma unroll
                for (int q = 0; q < 4; q++) acc[i][j][q] = 0.f;

        auto load_stage = [&](int c, int st_i) {
            const uint32_t st = sb + st_i * STAGE_BYTES;
            const int k0 = c * BK;
#pragma unroll
            for (int i = 0; i < 6; i++) {
                int g = i * GT + tid;
                int arr = g >> 9;                // 0:A 1:B1 2:B2
                int rem = g & 511;
                int row = rem >> 2, ch = rem & 3;
                const __half* src;
                if (arr == 0)      src = Ab + ((size_t)(tc * 128 + row) * K + k0 + ch * 8);
                else if (arr == 1) src = B1 + ((size_t)(n0 + row) * K + k0 + ch * 8);
                else               src = B2 + ((size_t)(n0 + row) * K + k0 + ch * 8);
                cp16(st + arr * 8192 + swz64((uint32_t)(row * 64 + ch * 16)), src);
            }
            cp_commit();
        };

        // prologue: 3 stages in flight
#pragma unroll
        for (int s = 0; s < 3; s++) {
            if (s < NC) load_stage(s, s); else cp_commit();
        }

        for (int c = 0; c < NC; c++) {
            cp_wait<2>();            // stage c complete
            __syncthreads();         // all warps done reading stage (c+4)&3 == c&3 slot's prior use
            if (c + 3 < NC) load_stage(c + 3, (c + 3) & 3);
            else cp_commit();

            const uint32_t st = sb + (c & 3) * STAGE_BYTES;
#pragma unroll
            for (int ks = 0; ks < 2; ks++) {
                const uint32_t cb = ks * 32 + (lane >> 4) * 16;
                uint32_t af[4][4];
#pragma unroll
                for (int mi = 0; mi < 4; mi++) {
                    uint32_t row = wm * 64 + mi * 16 + (lane & 15);
                    uint32_t off = swz64(row * 64 + cb);
                    ldm_x4(af[mi][0], af[mi][1], af[mi][2], af[mi][3], st + OFF_SA + off);
                }
                uint32_t b1f[4][2], b2f[4][2];
#pragma unroll
                for (int ni = 0; ni < 2; ni++) {
                    uint32_t row = wn * 32 + ni * 16 + (lane & 15);
                    uint32_t off = swz64(row * 64 + cb);
                    uint32_t r0, r1, r2, r3;
                    ldm_x4(r0, r1, r2, r3, st + OFF_SB1 + off);
                    b1f[2*ni][0] = r0; b1f[2*ni][1] = r2;
                    b1f[2*ni+1][0] = r1; b1f[2*ni+1][1] = r3;
                    ldm_x4(r0, r1, r2, r3, st + OFF_SB2 + off);
                    b2f[2*ni][0] = r0; b2f[2*ni][1] = r2;
                    b2f[2*ni+1][0] = r1; b2f[2*ni+1][1] = r3;
                }
#pragma unroll
                for (int mi = 0; mi < 4; mi++)
#pragma unroll
                    for (int nf = 0; nf < 4; nf++)
                        mma_f16(acc[mi][nf], af[mi], b1f[nf][0], b1f[nf][1]);
#pragma unroll
                for (int mi = 0; mi < 4; mi++)
#pragma unroll
                    for (int nf = 0; nf < 4; nf++)
                        mma_f16(acc[mi][nf], af[mi], b2f[nf][0], b2f[nf][1]);
            }
        }

        cp_wait<0>();
        __syncthreads();

        // dump accumulators: scanbuf[t_local][h_local]
        {
            const int group = lane >> 2, tid4 = lane & 3;
#pragma unroll
            for (int nf = 0; nf < 4; nf++) {
                int hc = wn * 32 + nf * 8 + tid4 * 2;
#pragma unroll
                for (int mi = 0; mi < 4; mi++) {
                    int tr = wm * 64 + mi * 16 + group;
                    float2 v0 = { acc[mi][nf][0], acc[mi][nf][1] };
                    float2 v1 = { acc[mi][nf][2], acc[mi][nf][3] };
                    *(float2*)&scanbuf[tr * SCAN_STRIDE + hc] = v0;
                    *(float2*)&scanbuf[(tr + 8) * SCAN_STRIDE + hc] = v1;
                }
            }
        }
        __syncthreads();

        // scan this chunk: threads 0..127, one h-col each; writes b-major
        if (tid < 128) {
#pragma unroll 1
            for (int t0 = 0; t0 < 128; t0 += 8) {
                float v[8];
#pragma unroll
                for (int j = 0; j < 8; j++)
                    v[j] = scanbuf[(t0 + j) * SCAN_STRIDE + tid];
#pragma unroll
                for (int j = 0; j < 8; j++) {
                    float y = v[j] + bb;
                    s_state = fmaxf(fmaf(uu, s_state, y), 0.f);
                    if (WRITE_NEXT) {
                        size_t m = (size_t)b * TT + (tc * 128 + t0 + j);
                        Anext[m * HH + n0 + tid] = __float2half_rn(s_state);
                    }
                    l_sum += s_state;
                    l_sq = fmaf(s_state, s_state, l_sq);
                }
            }
        }
        __syncthreads();
    }

    if (tid < 128) {
        if (!WRITE_NEXT) hlast[(size_t)b * HH + n0 + tid] = s_state;
        atomicAdd(&gsum[n0 + tid], l_sum);
        atomicAdd(&gsumsq[n0 + tid], l_sq);
    }
}

__global__ void final_kernel(const float* __restrict__ hl,
                             const float* __restrict__ Wout,
                             const float* __restrict__ bout,
                             float* __restrict__ out) {
    __shared__ float sh[HH];
    int b = blockIdx.x;
    for (int h = threadIdx.x; h < HH; h += blockDim.x)
        sh[h] = fmaf(hl[b * HH + h], g_scale[h], g_shift[h]);
    __syncthreads();
    int c = threadIdx.x;
    if (c < CC) {
        float acc = bout[c];
#pragma unroll 8
        for (int h = 0; h < HH; h++)
            acc = fmaf(sh[h], Wout[c * HH + h], acc);
        out[b * CC + c] = acc;
    }
}

extern "C" void kernel_launch(void* const* d_in, const int* in_sizes, int n_in,
                              void* d_out, int out_size) {
    const float* x     = (const float*)d_in[0];
    const float* W0    = (const float*)d_in[1];
    const float* b0    = (const float*)d_in[2];
    const float* Wh    = (const float*)d_in[3];
    const float* bh    = (const float*)d_in[4];
    const float* u     = (const float*)d_in[5];
    const float* gamma = (const float*)d_in[6];
    const float* beta  = (const float*)d_in[7];
    const float* Wout  = (const float*)d_in[8];
    const float* bout  = (const float*)d_in[9];
    float* out = (float*)d_out;

    float *beff, *sum, *sumsq, *hlast;
    __half *Aping, *Apong, *B1, *B2;
    cudaGetSymbolAddress((void**)&Aping, g_Aping);
    cudaGetSymbolAddress((void**)&Apong, g_Apong);
    cudaGetSymbolAddress((void**)&B1, g_B1);
    cudaGetSymbolAddress((void**)&B2, g_B2);
    cudaGetSymbolAddress((void**)&beff, g_beff);
    cudaGetSymbolAddress((void**)&sum, g_sum);
    cudaGetSymbolAddress((void**)&sumsq, g_sumsq);
    cudaGetSymbolAddress((void**)&hlast, g_hlast);

    cudaFuncSetAttribute(layer_fused<true>, cudaFuncAttributeMaxDynamicSharedMemorySize, FSMEM);
    cudaFuncSetAttribute(layer_fused<false>, cudaFuncAttributeMaxDynamicSharedMemorySize, FSMEM);

    // launch order: 0:prep_all 1:layer0 2:fold 3:layer1 <- ncu captures #3
    prep_all_kernel<<<(MM * K0P + 255) / 256, 256>>>(x, W0, b0);

    dim3 fgrid(NN / BN, BB);

    layer_fused<true><<<fgrid, GT, FSMEM>>>(Aping, B1, B2, beff, u, Apong,
                                            nullptr, sum, sumsq, K0P);
    __half* cur = Apong;
    __half* nxt = Aping;

    for (int l = 1; l < LL; l++) {
        const float* Wl  = Wh + (size_t)(l - 1) * HH * HH;
        const float* bhl = bh + (size_t)(l - 1) * HH;
        fold_all_kernel<<<HH, HH>>>(Wl, bhl, sum + (l - 1) * HH, sumsq + (l - 1) * HH,
                                    gamma + (l - 1) * HH, beta + (l - 1) * HH);
        if (l < LL - 1) {
            layer_fused<true><<<fgrid, GT, FSMEM>>>(cur, B1, B2, beff, u + l * HH, nxt,
                                                    nullptr, sum + l * HH, sumsq + l * HH, HH);
            __half* t = cur; cur = nxt; nxt = t;
        } else {
            layer_fused<false><<<fgrid, GT, FSMEM>>>(cur, B1, B2, beff, u + l * HH, nullptr,
                                                     hlast, sum + l * HH, sumsq + l * HH, HH);
        }
    }

    scale_shift_kernel<<<2, 256>>>(sum + (LL - 1) * HH, sumsq + (LL - 1) * HH,
                                   gamma + (LL - 1) * HH, beta + (LL - 1) * HH);
    final_kernel<<<BB, 64>>>(hlast, Wout, bout, out);
}

// round 12
// speedup vs baseline: 1.0873x; 1.0183x over previous
#include <cuda_runtime.h>
#include <cuda_fp16.h>
#include <cstdint>

#define TT 512
#define BB 128
#define HH 512
#define LL 6
#define CC 60
#define J3 75
#define K0P 128
#define BH (BB*HH)
#define MM (TT*BB)
#define NN 512
#define EPSBN 1e-5f

// fused layer kernel tiling: per CTA: one b, 128 h-cols, 4 t-chunks of 128
// 128 threads = 4 warps in 2x2 grid of 64x64 warp tiles
#define BM 128
#define BN 128
#define BK 32
#define GT 128
#define NSTAGE 4
#define STAGE_BYTES 24576   // A(8K)+B1(8K)+B2(8K)
#define OFF_SA  0
#define OFF_SB1 8192
#define OFF_SB2 16384
#define SCAN_STRIDE 136     // floats per row (bank-shift 8)
#define FSMEM (NSTAGE*STAGE_BYTES)   // 98304; scanbuf (69632) overlays stages 1-3

// activations stored b-major: A[(b*TT + t)*K + k]
__device__ __half g_Aping[(size_t)MM * HH];
__device__ __half g_Apong[(size_t)MM * HH];
__device__ __half g_B1[HH * HH];
__device__ __half g_B2[HH * HH];
__device__ float g_beff[HH];
__device__ float g_scale[HH];
__device__ float g_shift[HH];
__device__ float g_sum[LL * HH];
__device__ float g_sumsq[LL * HH];
__device__ float g_hlast[BH];

__device__ __forceinline__ uint32_t smem_u32(const void* p) {
    uint32_t a;
    asm("{ .reg .u64 t; cvta.to.shared.u64 t, %1; cvt.u32.u64 %0, t; }" : "=r"(a) : "l"(p));
    return a;
}
__device__ __forceinline__ uint32_t swz64(uint32_t off) { return off ^ ((off >> 3) & 0x30); }
__device__ __forceinline__ void cp16(uint32_t dst, const void* src) {
    asm volatile("cp.async.cg.shared.global [%0], [%1], 16;\n" :: "r"(dst), "l"(src));
}
__device__ __forceinline__ void cp_commit() { asm volatile("cp.async.commit_group;\n" ::: "memory"); }
template <int N> __device__ __forceinline__ void cp_wait() {
    asm volatile("cp.async.wait_group %0;\n" :: "n"(N) : "memory");
}
__device__ __forceinline__ void ldm_x4(uint32_t& r0, uint32_t& r1, uint32_t& r2, uint32_t& r3,
                                       uint32_t addr) {
    asm volatile("ldmatrix.sync.aligned.m8n8.x4.shared.b16 {%0,%1,%2,%3}, [%4];"
        : "=r"(r0), "=r"(r1), "=r"(r2), "=r"(r3) : "r"(addr));
}
__device__ __forceinline__ void mma_f16(float* c, const uint32_t* a, uint32_t b0, uint32_t b1) {
    asm volatile("mma.sync.aligned.m16n8k16.row.col.f32.f16.f16.f32 "
        "{%0,%1,%2,%3}, {%4,%5,%6,%7}, {%8,%9}, {%0,%1,%2,%3};"
        : "+f"(c[0]), "+f"(c[1]), "+f"(c[2]), "+f"(c[3])
        : "r"(a[0]), "r"(a[1]), "r"(a[2]), "r"(a[3]), "r"(b0), "r"(b1));
}
__device__ __forceinline__ void hsplit(float v, __half& h1, __half& h2) {
    h1 = __float2half_rn(v);
    h2 = __float2half_rn(v - __half2float(h1));
}

// merged prep: zero stats + pad x (b-major) + split W0 + copy b0
__global__ void prep_all_kernel(const float* __restrict__ x,
                                const float* __restrict__ W0,
                                const float* __restrict__ b0) {
    int idx = blockIdx.x * blockDim.x + threadIdx.x;
    if (idx < LL * HH) { g_sum[idx] = 0.f; g_sumsq[idx] = 0.f; }
    if (idx < HH) g_beff[idx] = b0[idx];
    if (idx < HH * K0P) {
        int n = idx >> 7, k = idx & 127;
        float v = (k < J3) ? W0[n * J3 + k] : 0.f;
        __half h1, h2; hsplit(v, h1, h2);
        g_B1[idx] = h1; g_B2[idx] = h2;
    }
    if (idx < MM * K0P) {
        int k = idx & 127;
        int bt = idx >> 7;          // b*TT + t
        int b = bt >> 9, t = bt & (TT - 1);
        float v = (k < J3) ? x[(size_t)(t * BB + b) * J3 + k] : 0.f;
        g_Aping[idx] = __float2half_rn(v);
    }
}

__global__ void scale_shift_kernel(const float* __restrict__ sum,
                                   const float* __restrict__ sumsq,
                                   const float* __restrict__ gamma,
                                   const float* __restrict__ beta) {
    int h = blockIdx.x * blockDim.x + threadIdx.x;
    if (h >= HH) return;
    const float inv = 1.0f / (float)(TT * BB);
    float mean = sum[h] * inv;
    float var  = sumsq[h] * inv - mean * mean;
    float sc   = gamma[h] * rsqrtf(var + EPSBN);
    g_scale[h] = sc;
    g_shift[h] = beta[h] - mean * sc;
}

// one block per output row h: BN affine in smem, fold into W row + bias (shuffle reduce)
__global__ __launch_bounds__(HH) void fold_all_kernel(
    const float* __restrict__ W, const float* __restrict__ bh,
    const float* __restrict__ sum, const float* __restrict__ sumsq,
    const float* __restrict__ gamma, const float* __restrict__ beta) {
    __shared__ float s_scale[HH], s_shift[HH], s_warp[16];
    const int t = threadIdx.x;
    {
        const float inv = 1.0f / (float)(TT * BB);
        float mean = sum[t] * inv;
        float var  = sumsq[t] * inv - mean * mean;
        float sc   = gamma[t] * rsqrtf(var + EPSBN);
        s_scale[t] = sc;
        s_shift[t] = beta[t] - mean * sc;
    }
    __syncthreads();
    const int h = blockIdx.x;
    float w = W[h * HH + t];
    float v = w * s_scale[t];
    __half h1, h2; hsplit(v, h1, h2);
    g_B1[h * HH + t] = h1;
    g_B2[h * HH + t] = h2;
    float r = w * s_shift[t];
#pragma unroll
    for (int o = 16; o > 0; o >>= 1) r += __shfl_down_sync(0xFFFFFFFFu, r, o);
    if ((t & 31) == 0) s_warp[t >> 5] = r;
    __syncthreads();
    if (t < 32) {
        float x2 = (t < 16) ? s_warp[t] : 0.f;
#pragma unroll
        for (int o = 8; o > 0; o >>= 1) x2 += __shfl_down_sync(0xFFFFFFFFu, x2, o);
        if (t == 0) g_beff[h] = bh[h] + x2;
    }
}

// Fused layer: per CTA (n-tile, b): for 4 t-chunks: GEMM 128x128 -> smem -> scan
// 4 warps, 2x2 grid of 64x64 warp tiles; safe wait->barrier->ldm ordering.
template <bool WRITE_NEXT>
__global__ __launch_bounds__(GT, 2) void layer_fused(
    const __half* __restrict__ A,
    const __half* __restrict__ B1, const __half* __restrict__ B2,
    const float* __restrict__ bias, const float* __restrict__ u,
    __half* __restrict__ Anext, float* __restrict__ hlast,
    float* __restrict__ gsum, float* __restrict__ gsumsq, int K) {
    extern __shared__ __align__(128) char smem[];
    const uint32_t sb = smem_u32(smem);
    float* scanbuf = (float*)(smem + STAGE_BYTES);    // overlays stages 1-3
    const int tid = threadIdx.x, wid = tid >> 5, lane = tid & 31;
    const int n0 = blockIdx.x * BN;
    const int b  = blockIdx.y;
    const int NC = K / BK;
    const int wm = wid & 1;        // 2 m-warps -> 64 t-rows each
    const int wn = wid >> 1;       // 2 n-warps -> 64 h-cols each
    const __half* Ab = A + (size_t)b * TT * K;        // contiguous [TT x K] block

    float s_state = 0.f, l_sum = 0.f, l_sq = 0.f;
    const float uu = u[n0 + tid];
    const float bb = bias[n0 + tid];

    auto load_stage = [&](int tchunk, int c, int sloti) {
        const uint32_t st = sb + sloti * STAGE_BYTES;
        const int k0 = c * BK;
#pragma unroll
        for (int i = 0; i < 12; i++) {
            int g = i * GT + tid;            // 0..1535
            int arr = g >> 9;                // 0:A 1:B1 2:B2
            int rem = g & 511;
            int row = rem >> 2, ch = rem & 3;
            const __half* src;
            if (arr == 0)      src = Ab + ((size_t)(tchunk * 128 + row) * K + k0 + ch * 8);
            else if (arr == 1) src = B1 + ((size_t)(n0 + row) * K + k0 + ch * 8);
            else               src = B2 + ((size_t)(n0 + row) * K + k0 + ch * 8);
            cp16(st + arr * 8192 + swz64((uint32_t)(row * 64 + ch * 16)), src);
        }
        cp_commit();
    };

    for (int tc = 0; tc < 4; tc++) {
        float acc[4][8][4];
#pragma unroll
        for (int i = 0; i < 4; i++)
#pragma unroll
            for (int j = 0; j < 8; j++)
#pragma unroll
                for (int q = 0; q < 4; q++) acc[i][j][q] = 0.f;

        // prologue: stage0 of this chunk was issued before the previous scan
        if (tc == 0) load_stage(0, 0, 0);
        load_stage(tc, 1, 1);
        load_stage(tc, 2, 2);

        for (int c = 0; c < NC; c++) {
            cp_wait<2>();            // own groups for stage c done
            __syncthreads();         // cross-warp visibility + slot (c+3)&3 free
            if (c + 3 < NC) load_stage(tc, c + 3, (c + 3) & 3);
            else cp_commit();

            const uint32_t st = sb + (c & 3) * STAGE_BYTES;
#pragma unroll
            for (int ks = 0; ks < 2; ks++) {
                const uint32_t cb = ks * 32 + (lane >> 4) * 16;
                uint32_t af[4][4];
#pragma unroll
                for (int mi = 0; mi < 4; mi++) {
                    uint32_t row = wm * 64 + mi * 16 + (lane & 15);
                    uint32_t off = swz64(row * 64 + cb);
                    ldm_x4(af[mi][0], af[mi][1], af[mi][2], af[mi][3], st + OFF_SA + off);
                }
                uint32_t b1f[8][2], b2f[8][2];
#pragma unroll
                for (int ni = 0; ni < 4; ni++) {
                    uint32_t row = wn * 64 + ni * 16 + (lane & 15);
                    uint32_t off = swz64(row * 64 + cb);
                    uint32_t r0, r1, r2, r3;
                    ldm_x4(r0, r1, r2, r3, st + OFF_SB1 + off);
                    b1f[2*ni][0] = r0; b1f[2*ni][1] = r2;
                    b1f[2*ni+1][0] = r1; b1f[2*ni+1][1] = r3;
                    ldm_x4(r0, r1, r2, r3, st + OFF_SB2 + off);
                    b2f[2*ni][0] = r0; b2f[2*ni][1] = r2;
                    b2f[2*ni+1][0] = r1; b2f[2*ni+1][1] = r3;
                }
#pragma unroll
                for (int mi = 0; mi < 4; mi++)
#pragma unroll
                    for (int nf = 0; nf < 8; nf++)
                        mma_f16(acc[mi][nf], af[mi], b1f[nf][0], b1f[nf][1]);
#pragma unroll
                for (int mi = 0; mi < 4; mi++)
#pragma unroll
                    for (int nf = 0; nf < 8; nf++)
                        mma_f16(acc[mi][nf], af[mi], b2f[nf][0], b2f[nf][1]);
            }
        }

        cp_wait<0>();
        __syncthreads();

        // dump accumulators: scanbuf[t_local][h_local] (stages 1-3 region)
        {
            const int group = lane >> 2, tid4 = lane & 3;
#pragma unroll
            for (int nf = 0; nf < 8; nf++) {
                int hc = wn * 64 + nf * 8 + tid4 * 2;
#pragma unroll
                for (int mi = 0; mi < 4; mi++) {
                    int tr = wm * 64 + mi * 16 + group;
                    float2 v0 = { acc[mi][nf][0], acc[mi][nf][1] };
                    float2 v1 = { acc[mi][nf][2], acc[mi][nf][3] };
                    *(float2*)&scanbuf[tr * SCAN_STRIDE + hc] = v0;
                    *(float2*)&scanbuf[(tr + 8) * SCAN_STRIDE + hc] = v1;
                }
            }
        }
        __syncthreads();

        // issue next chunk's stage-0 load (slot 0, disjoint from scanbuf) under the scan
        if (tc < 3) load_stage(tc + 1, 0, 0);

        // scan this chunk: all 128 threads, one h-col each; writes b-major
        {
#pragma unroll 1
            for (int t0 = 0; t0 < 128; t0 += 8) {
                float v[8];
#pragma unroll
                for (int j = 0; j < 8; j++)
                    v[j] = scanbuf[(t0 + j) * SCAN_STRIDE + tid] + bb;
#pragma unroll
                for (int j = 0; j < 8; j++) {
                    s_state = fmaxf(fmaf(uu, s_state, v[j]), 0.f);
                    if (WRITE_NEXT) {
                        size_t m = (size_t)b * TT + (tc * 128 + t0 + j);
                        Anext[m * HH + n0 + tid] = __float2half_rn(s_state);
                    }
                    l_sum += s_state;
                    l_sq = fmaf(s_state, s_state, l_sq);
                }
            }
        }
        __syncthreads();
    }

    {
        if (!WRITE_NEXT) hlast[(size_t)b * HH + n0 + tid] = s_state;
        atomicAdd(&gsum[n0 + tid], l_sum);
        atomicAdd(&gsumsq[n0 + tid], l_sq);
    }
}

__global__ void final_kernel(const float* __restrict__ hl,
                             const float* __restrict__ Wout,
                             const float* __restrict__ bout,
                             float* __restrict__ out) {
    __shared__ float sh[HH];
    int b = blockIdx.x;
    for (int h = threadIdx.x; h < HH; h += blockDim.x)
        sh[h] = fmaf(hl[b * HH + h], g_scale[h], g_shift[h]);
    __syncthreads();
    int c = threadIdx.x;
    if (c < CC) {
        float acc = bout[c];
#pragma unroll 8
        for (int h = 0; h < HH; h++)
            acc = fmaf(sh[h], Wout[c * HH + h], acc);
        out[b * CC + c] = acc;
    }
}

extern "C" void kernel_launch(void* const* d_in, const int* in_sizes, int n_in,
                              void* d_out, int out_size) {
    const float* x     = (const float*)d_in[0];
    const float* W0    = (const float*)d_in[1];
    const float* b0    = (const float*)d_in[2];
    const float* Wh    = (const float*)d_in[3];
    const float* bh    = (const float*)d_in[4];
    const float* u     = (const float*)d_in[5];
    const float* gamma = (const float*)d_in[6];
    const float* beta  = (const float*)d_in[7];
    const float* Wout  = (const float*)d_in[8];
    const float* bout  = (const float*)d_in[9];
    float* out = (float*)d_out;

    float *beff, *sum, *sumsq, *hlast;
    __half *Aping, *Apong, *B1, *B2;
    cudaGetSymbolAddress((void**)&Aping, g_Aping);
    cudaGetSymbolAddress((void**)&Apong, g_Apong);
    cudaGetSymbolAddress((void**)&B1, g_B1);
    cudaGetSymbolAddress((void**)&B2, g_B2);
    cudaGetSymbolAddress((void**)&beff, g_beff);
    cudaGetSymbolAddress((void**)&sum, g_sum);
    cudaGetSymbolAddress((void**)&sumsq, g_sumsq);
    cudaGetSymbolAddress((void**)&hlast, g_hlast);

    cudaFuncSetAttribute(layer_fused<true>, cudaFuncAttributeMaxDynamicSharedMemorySize, FSMEM);
    cudaFuncSetAttribute(layer_fused<false>, cudaFuncAttributeMaxDynamicSharedMemorySize, FSMEM);

    // launch order: 0:prep_all 1:layer0 2:fold 3:layer1 <- ncu captures #3
    prep_all_kernel<<<(MM * K0P + 255) / 256, 256>>>(x, W0, b0);

    dim3 fgrid(NN / BN, BB);

    layer_fused<true><<<fgrid, GT, FSMEM>>>(Aping, B1, B2, beff, u, Apong,
                                            nullptr, sum, sumsq, K0P);
    __half* cur = Apong;
    __half* nxt = Aping;

    for (int l = 1; l < LL; l++) {
        const float* Wl  = Wh + (size_t)(l - 1) * HH * HH;
        const float* bhl = bh + (size_t)(l - 1) * HH;
        fold_all_kernel<<<HH, HH>>>(Wl, bhl, sum + (l - 1) * HH, sumsq + (l - 1) * HH,
                                    gamma + (l - 1) * HH, beta + (l - 1) * HH);
        if (l < LL - 1) {
            layer_fused<true><<<fgrid, GT, FSMEM>>>(cur, B1, B2, beff, u + l * HH, nxt,
                                                    nullptr, sum + l * HH, sumsq + l * HH, HH);
            __half* t = cur; cur = nxt; nxt = t;
        } else {
            layer_fused<false><<<fgrid, GT, FSMEM>>>(cur, B1, B2, beff, u + l * HH, nullptr,
                                                     hlast, sum + l * HH, sumsq + l * HH, HH);
        }
    }

    scale_shift_kernel<<<2, 256>>>(sum + (LL - 1) * HH, sumsq + (LL - 1) * HH,
                                   gamma + (LL - 1) * HH, beta + (LL - 1) * HH);
    final_kernel<<<BB, 64>>>(hlast, Wout, bout, out);
}

// round 13
// speedup vs baseline: 1.1706x; 1.0766x over previous
#include <cuda_runtime.h>
#include <cuda_fp16.h>
#include <cstdint>

#define TT 512
#define BB 128
#define HH 512
#define LL 6
#define CC 60
#define J3 75
#define K0P 128
#define BH (BB*HH)
#define MM (TT*BB)
#define NN 512
#define EPSBN 1e-5f

// fused layer: per CTA: one b, 64 h-cols, 4 t-chunks of 128
// 128 threads = 4 warps in 2x2 grid of 64x32 warp tiles
#define BM 128
#define BN 64
#define BK 32
#define GT 128
#define NSTAGE 4
#define STAGE_BYTES 16384   // A(8K)+B1(4K)+B2(4K)
#define OFF_SA  0
#define OFF_SB1 8192
#define OFF_SB2 12288
#define SCAN_STRIDE 72      // floats per row (64 + pad 8)
#define FSMEM (NSTAGE*STAGE_BYTES)   // 65536; scanbuf (36864) overlays stages 1-3

// activations stored b-major: A[(b*TT + t)*K + k]
__device__ __half g_Aping[(size_t)MM * HH];
__device__ __half g_Apong[(size_t)MM * HH];
__device__ __half g_B1[HH * HH];
__device__ __half g_B2[HH * HH];
__device__ float g_beff[HH];
__device__ float g_scale[HH];
__device__ float g_shift[HH];
__device__ float g_sum[LL * HH];
__device__ float g_sumsq[LL * HH];
__device__ float g_hlast[BH];

__device__ __forceinline__ uint32_t smem_u32(const void* p) {
    uint32_t a;
    asm("{ .reg .u64 t; cvta.to.shared.u64 t, %1; cvt.u32.u64 %0, t; }" : "=r"(a) : "l"(p));
    return a;
}
__device__ __forceinline__ uint32_t swz64(uint32_t off) { return off ^ ((off >> 3) & 0x30); }
__device__ __forceinline__ void cp16(uint32_t dst, const void* src) {
    asm volatile("cp.async.cg.shared.global [%0], [%1], 16;\n" :: "r"(dst), "l"(src));
}
__device__ __forceinline__ void cp_commit() { asm volatile("cp.async.commit_group;\n" ::: "memory"); }
template <int N> __device__ __forceinline__ void cp_wait() {
    asm volatile("cp.async.wait_group %0;\n" :: "n"(N) : "memory");
}
__device__ __forceinline__ void ldm_x4(uint32_t& r0, uint32_t& r1, uint32_t& r2, uint32_t& r3,
                                       uint32_t addr) {
    asm volatile("ldmatrix.sync.aligned.m8n8.x4.shared.b16 {%0,%1,%2,%3}, [%4];"
        : "=r"(r0), "=r"(r1), "=r"(r2), "=r"(r3) : "r"(addr));
}
__device__ __forceinline__ void mma_f16(float* c, const uint32_t* a, uint32_t b0, uint32_t b1) {
    asm volatile("mma.sync.aligned.m16n8k16.row.col.f32.f16.f16.f32 "
        "{%0,%1,%2,%3}, {%4,%5,%6,%7}, {%8,%9}, {%0,%1,%2,%3};"
        : "+f"(c[0]), "+f"(c[1]), "+f"(c[2]), "+f"(c[3])
        : "r"(a[0]), "r"(a[1]), "r"(a[2]), "r"(a[3]), "r"(b0), "r"(b1));
}
__device__ __forceinline__ void hsplit(float v, __half& h1, __half& h2) {
    h1 = __float2half_rn(v);
    h2 = __float2half_rn(v - __half2float(h1));
}

// merged prep: zero stats + pad x (b-major) + split W0 + copy b0
__global__ void prep_all_kernel(const float* __restrict__ x,
                                const float* __restrict__ W0,
                                const float* __restrict__ b0) {
    int idx = blockIdx.x * blockDim.x + threadIdx.x;
    if (idx < LL * HH) { g_sum[idx] = 0.f; g_sumsq[idx] = 0.f; }
    if (idx < HH) g_beff[idx] = b0[idx];
    if (idx < HH * K0P) {
        int n = idx >> 7, k = idx & 127;
        float v = (k < J3) ? W0[n * J3 + k] : 0.f;
        __half h1, h2; hsplit(v, h1, h2);
        g_B1[idx] = h1; g_B2[idx] = h2;
    }
    if (idx < MM * K0P) {
        int k = idx & 127;
        int bt = idx >> 7;          // b*TT + t
        int b = bt >> 9, t = bt & (TT - 1);
        float v = (k < J3) ? x[(size_t)(t * BB + b) * J3 + k] : 0.f;
        g_Aping[idx] = __float2half_rn(v);
    }
}

__global__ void scale_shift_kernel(const float* __restrict__ sum,
                                   const float* __restrict__ sumsq,
                                   const float* __restrict__ gamma,
                                   const float* __restrict__ beta) {
    int h = blockIdx.x * blockDim.x + threadIdx.x;
    if (h >= HH) return;
    const float inv = 1.0f / (float)(TT * BB);
    float mean = sum[h] * inv;
    float var  = sumsq[h] * inv - mean * mean;
    float sc   = gamma[h] * rsqrtf(var + EPSBN);
    g_scale[h] = sc;
    g_shift[h] = beta[h] - mean * sc;
}

// one block per output row h: BN affine in smem, fold into W row + bias (shuffle reduce)
__global__ __launch_bounds__(HH) void fold_all_kernel(
    const float* __restrict__ W, const float* __restrict__ bh,
    const float* __restrict__ sum, const float* __restrict__ sumsq,
    const float* __restrict__ gamma, const float* __restrict__ beta) {
    __shared__ float s_scale[HH], s_shift[HH], s_warp[16];
    const int t = threadIdx.x;
    {
        const float inv = 1.0f / (float)(TT * BB);
        float mean = sum[t] * inv;
        float var  = sumsq[t] * inv - mean * mean;
        float sc   = gamma[t] * rsqrtf(var + EPSBN);
        s_scale[t] = sc;
        s_shift[t] = beta[t] - mean * sc;
    }
    __syncthreads();
    const int h = blockIdx.x;
    float w = W[h * HH + t];
    float v = w * s_scale[t];
    __half h1, h2; hsplit(v, h1, h2);
    g_B1[h * HH + t] = h1;
    g_B2[h * HH + t] = h2;
    float r = w * s_shift[t];
#pragma unroll
    for (int o = 16; o > 0; o >>= 1) r += __shfl_down_sync(0xFFFFFFFFu, r, o);
    if ((t & 31) == 0) s_warp[t >> 5] = r;
    __syncthreads();
    if (t < 32) {
        float x2 = (t < 16) ? s_warp[t] : 0.f;
#pragma unroll
        for (int o = 8; o > 0; o >>= 1) x2 += __shfl_down_sync(0xFFFFFFFFu, x2, o);
        if (t == 0) g_beff[h] = bh[h] + x2;
    }
}

// Fused layer: per CTA (n-tile of 64, b): 4 t-chunks: GEMM 128x64 -> smem -> scan
// 4 warps (2m x 2n of 64x32 tiles), 3 CTAs/SM
template <bool WRITE_NEXT>
__global__ __launch_bounds__(GT, 3) void layer_fused(
    const __half* __restrict__ A,
    const __half* __restrict__ B1, const __half* __restrict__ B2,
    const float* __restrict__ bias, const float* __restrict__ u,
    __half* __restrict__ Anext, float* __restrict__ hlast,
    float* __restrict__ gsum, float* __restrict__ gsumsq, int K) {
    extern __shared__ __align__(128) char smem[];
    const uint32_t sb = smem_u32(smem);
    float* scanbuf = (float*)(smem + STAGE_BYTES);    // overlays stages 1-3
    const int tid = threadIdx.x, wid = tid >> 5, lane = tid & 31;
    const int n0 = blockIdx.x * BN;
    const int b  = blockIdx.y;
    const int NC = K / BK;
    const int wm = wid & 1;        // 2 m-warps -> 64 t-rows each
    const int wn = wid >> 1;       // 2 n-warps -> 32 h-cols each
    const __half* Ab = A + (size_t)b * TT * K;        // contiguous [TT x K] block

    float s_state = 0.f, l_sum = 0.f, l_sq = 0.f, uu = 0.f, bb = 0.f;
    if (tid < BN) { uu = u[n0 + tid]; bb = bias[n0 + tid]; }

    auto load_stage = [&](int tchunk, int c, int sloti) {
        const uint32_t st = sb + sloti * STAGE_BYTES;
        const int k0 = c * BK;
        // 1024 cp16 ops: A 512 (128 rows x 4 segs), B1 256, B2 256
#pragma unroll
        for (int i = 0; i < 8; i++) {
            int g = i * GT + tid;            // 0..1023
            const __half* src;
            uint32_t dst;
            if (g < 512) {
                int row = g >> 2, ch = g & 3;
                src = Ab + ((size_t)(tchunk * 128 + row) * K + k0 + ch * 8);
                dst = st + OFF_SA + swz64((uint32_t)(row * 64 + ch * 16));
            } else {
                int gg = g - 512;
                int arr = gg >> 8;           // 0:B1 1:B2
                int rem = gg & 255;
                int row = rem >> 2, ch = rem & 3;
                src = (arr ? B2 : B1) + ((size_t)(n0 + row) * K + k0 + ch * 8);
                dst = st + (arr ? OFF_SB2 : OFF_SB1) + swz64((uint32_t)(row * 64 + ch * 16));
            }
            cp16(dst, src);
        }
        cp_commit();
    };

    for (int tc = 0; tc < 4; tc++) {
        float acc[4][4][4];
#pragma unroll
        for (int i = 0; i < 4; i++)
#pragma unroll
            for (int j = 0; j < 4; j++)
#pragma unroll
                for (int q = 0; q < 4; q++) acc[i][j][q] = 0.f;

        // prologue: stage0 of this chunk issued before the previous scan (except tc==0)
        if (tc == 0) load_stage(0, 0, 0);
        load_stage(tc, 1, 1);
        load_stage(tc, 2, 2);

        for (int c = 0; c < NC; c++) {
            cp_wait<2>();            // own groups for stage c done
            __syncthreads();         // cross-warp visibility + slot (c+3)&3 free
            if (c + 3 < NC) load_stage(tc, c + 3, (c + 3) & 3);
            else cp_commit();

            const uint32_t st = sb + (c & 3) * STAGE_BYTES;
#pragma unroll
            for (int ks = 0; ks < 2; ks++) {
                const uint32_t cb = ks * 32 + (lane >> 4) * 16;
                uint32_t af[4][4];
#pragma unroll
                for (int mi = 0; mi < 4; mi++) {
                    uint32_t row = wm * 64 + mi * 16 + (lane & 15);
                    uint32_t off = swz64(row * 64 + cb);
                    ldm_x4(af[mi][0], af[mi][1], af[mi][2], af[mi][3], st + OFF_SA + off);
                }
                uint32_t b1f[4][2], b2f[4][2];
#pragma unroll
                for (int ni = 0; ni < 2; ni++) {
                    uint32_t row = wn * 32 + ni * 16 + (lane & 15);
                    uint32_t off = swz64(row * 64 + cb);
                    uint32_t r0, r1, r2, r3;
                    ldm_x4(r0, r1, r2, r3, st + OFF_SB1 + off);
                    b1f[2*ni][0] = r0; b1f[2*ni][1] = r2;
                    b1f[2*ni+1][0] = r1; b1f[2*ni+1][1] = r3;
                    ldm_x4(r0, r1, r2, r3, st + OFF_SB2 + off);
                    b2f[2*ni][0] = r0; b2f[2*ni][1] = r2;
                    b2f[2*ni+1][0] = r1; b2f[2*ni+1][1] = r3;
                }
#pragma unroll
                for (int mi = 0; mi < 4; mi++)
#pragma unroll
                    for (int nf = 0; nf < 4; nf++)
                        mma_f16(acc[mi][nf], af[mi], b1f[nf][0], b1f[nf][1]);
#pragma unroll
                for (int mi = 0; mi < 4; mi++)
#pragma unroll
                    for (int nf = 0; nf < 4; nf++)
                        mma_f16(acc[mi][nf], af[mi], b2f[nf][0], b2f[nf][1]);
            }
        }

        cp_wait<0>();
        __syncthreads();

        // dump accumulators: scanbuf[t_local][h_local] (stages 1-3 region)
        {
            const int group = lane >> 2, tid4 = lane & 3;
#pragma unroll
            for (int nf = 0; nf < 4; nf++) {
                int hc = wn * 32 + nf * 8 + tid4 * 2;
#pragma unroll
                for (int mi = 0; mi < 4; mi++) {
                    int tr = wm * 64 + mi * 16 + group;
                    float2 v0 = { acc[mi][nf][0], acc[mi][nf][1] };
                    float2 v1 = { acc[mi][nf][2], acc[mi][nf][3] };
                    *(float2*)&scanbuf[tr * SCAN_STRIDE + hc] = v0;
                    *(float2*)&scanbuf[(tr + 8) * SCAN_STRIDE + hc] = v1;
                }
            }
        }
        __syncthreads();

        // issue next chunk's stage-0 load (slot 0, disjoint from scanbuf) under the scan
        if (tc < 3) load_stage(tc + 1, 0, 0);

        // scan this chunk: threads 0..63, one h-col each; writes b-major
        if (tid < BN) {
#pragma unroll 1
            for (int t0 = 0; t0 < 128; t0 += 8) {
                float v[8];
#pragma unroll
                for (int j = 0; j < 8; j++)
                    v[j] = scanbuf[(t0 + j) * SCAN_STRIDE + tid] + bb;
#pragma unroll
                for (int j = 0; j < 8; j++) {
                    s_state = fmaxf(fmaf(uu, s_state, v[j]), 0.f);
                    if (WRITE_NEXT) {
                        size_t m = (size_t)b * TT + (tc * 128 + t0 + j);
                        Anext[m * HH + n0 + tid] = __float2half_rn(s_state);
                    }
                    l_sum += s_state;
                    l_sq = fmaf(s_state, s_state, l_sq);
                }
            }
        }
        __syncthreads();
    }

    if (tid < BN) {
        if (!WRITE_NEXT) hlast[(size_t)b * HH + n0 + tid] = s_state;
        atomicAdd(&gsum[n0 + tid], l_sum);
        atomicAdd(&gsumsq[n0 + tid], l_sq);
    }
}

__global__ void final_kernel(const float* __restrict__ hl,
                             const float* __restrict__ Wout,
                             const float* __restrict__ bout,
                             float* __restrict__ out) {
    __shared__ float sh[HH];
    int b = blockIdx.x;
    for (int h = threadIdx.x; h < HH; h += blockDim.x)
        sh[h] = fmaf(hl[b * HH + h], g_scale[h], g_shift[h]);
    __syncthreads();
    int c = threadIdx.x;
    if (c < CC) {
        float acc = bout[c];
#pragma unroll 8
        for (int h = 0; h < HH; h++)
            acc = fmaf(sh[h], Wout[c * HH + h], acc);
        out[b * CC + c] = acc;
    }
}

extern "C" void kernel_launch(void* const* d_in, const int* in_sizes, int n_in,
                              void* d_out, int out_size) {
    const float* x     = (const float*)d_in[0];
    const float* W0    = (const float*)d_in[1];
    const float* b0    = (const float*)d_in[2];
    const float* Wh    = (const float*)d_in[3];
    const float* bh    = (const float*)d_in[4];
    const float* u     = (const float*)d_in[5];
    const float* gamma = (const float*)d_in[6];
    const float* beta  = (const float*)d_in[7];
    const float* Wout  = (const float*)d_in[8];
    const float* bout  = (const float*)d_in[9];
    float* out = (float*)d_out;

    float *beff, *sum, *sumsq, *hlast;
    __half *Aping, *Apong, *B1, *B2;
    cudaGetSymbolAddress((void**)&Aping, g_Aping);
    cudaGetSymbolAddress((void**)&Apong, g_Apong);
    cudaGetSymbolAddress((void**)&B1, g_B1);
    cudaGetSymbolAddress((void**)&B2, g_B2);
    cudaGetSymbolAddress((void**)&beff, g_beff);
    cudaGetSymbolAddress((void**)&sum, g_sum);
    cudaGetSymbolAddress((void**)&sumsq, g_sumsq);
    cudaGetSymbolAddress((void**)&hlast, g_hlast);

    cudaFuncSetAttribute(layer_fused<true>, cudaFuncAttributeMaxDynamicSharedMemorySize, FSMEM);
    cudaFuncSetAttribute(layer_fused<false>, cudaFuncAttributeMaxDynamicSharedMemorySize, FSMEM);

    // launch order: 0:prep_all 1:layer0 2:fold 3:layer1 <- ncu captures #3
    prep_all_kernel<<<(MM * K0P + 255) / 256, 256>>>(x, W0, b0);

    dim3 fgrid(NN / BN, BB);

    layer_fused<true><<<fgrid, GT, FSMEM>>>(Aping, B1, B2, beff, u, Apong,
                                            nullptr, sum, sumsq, K0P);
    __half* cur = Apong;
    __half* nxt = Aping;

    for (int l = 1; l < LL; l++) {
        const float* Wl  = Wh + (size_t)(l - 1) * HH * HH;
        const float* bhl = bh + (size_t)(l - 1) * HH;
        fold_all_kernel<<<HH, HH>>>(Wl, bhl, sum + (l - 1) * HH, sumsq + (l - 1) * HH,
                                    gamma + (l - 1) * HH, beta + (l - 1) * HH);
        if (l < LL - 1) {
            layer_fused<true><<<fgrid, GT, FSMEM>>>(cur, B1, B2, beff, u + l * HH, nxt,
                                                    nullptr, sum + l * HH, sumsq + l * HH, HH);
            __half* t = cur; cur = nxt; nxt = t;
        } else {
            layer_fused<false><<<fgrid, GT, FSMEM>>>(cur, B1, B2, beff, u + l * HH, nullptr,
                                                     hlast, sum + l * HH, sumsq + l * HH, HH);
        }
    }

    scale_shift_kernel<<<2, 256>>>(sum + (LL - 1) * HH, sumsq + (LL - 1) * HH,
                                   gamma + (LL - 1) * HH, beta + (LL - 1) * HH);
    final_kernel<<<BB, 64>>>(hlast, Wout, bout, out);
}

// round 15
// speedup vs baseline: 1.2353x; 1.0553x over previous
#include <cuda_runtime.h>
#include <cuda_fp16.h>
#include <cstdint>

#define TT 512
#define BB 128
#define HH 512
#define LL 6
#define CC 60
#define J3 75
#define K0P 128
#define BH (BB*HH)
#define MM (TT*BB)
#define NN 512
#define EPSBN 1e-5f

// fused layer: per CTA: one b, 64 h-cols, 4 t-chunks of 128
// 128 threads = 4 warps in 2x2 grid of 64x32 warp tiles
#define BM 128
#define BN 64
#define BK 32
#define GT 128
#define NSTAGE 4
#define STAGE_BYTES 16384   // A(8K)+B1(4K)+B2(4K)
#define OFF_SA  0
#define OFF_SB1 8192
#define OFF_SB2 12288
#define SCAN_STRIDE 72      // floats per row (64 + pad 8)
#define FSMEM (NSTAGE*STAGE_BYTES)   // 65536; scanbuf (36864) overlays stages 1-3

// activations stored b-major: A[(b*TT + t)*K + k]
__device__ __half g_Aping[(size_t)MM * HH];
__device__ __half g_Apong[(size_t)MM * HH];
__device__ __half g_B1[HH * HH];
__device__ __half g_B2[HH * HH];
__device__ float g_beff[HH];
__device__ float g_scale[HH];
__device__ float g_shift[HH];
__device__ float g_sum[LL * HH];
__device__ float g_sumsq[LL * HH];
__device__ float g_hlast[BH];

__device__ __forceinline__ uint32_t smem_u32(const void* p) {
    uint32_t a;
    asm("{ .reg .u64 t; cvta.to.shared.u64 t, %1; cvt.u32.u64 %0, t; }" : "=r"(a) : "l"(p));
    return a;
}
__device__ __forceinline__ uint32_t swz64(uint32_t off) { return off ^ ((off >> 3) & 0x30); }
__device__ __forceinline__ void cp16(uint32_t dst, const void* src) {
    asm volatile("cp.async.cg.shared.global [%0], [%1], 16;\n" :: "r"(dst), "l"(src));
}
__device__ __forceinline__ void cp_commit() { asm volatile("cp.async.commit_group;\n" ::: "memory"); }
template <int N> __device__ __forceinline__ void cp_wait() {
    asm volatile("cp.async.wait_group %0;\n" :: "n"(N) : "memory");
}
__device__ __forceinline__ void ldm_x4(uint32_t& r0, uint32_t& r1, uint32_t& r2, uint32_t& r3,
                                       uint32_t addr) {
    asm volatile("ldmatrix.sync.aligned.m8n8.x4.shared.b16 {%0,%1,%2,%3}, [%4];"
        : "=r"(r0), "=r"(r1), "=r"(r2), "=r"(r3) : "r"(addr));
}
__device__ __forceinline__ void mma_f16(float* c, const uint32_t* a, uint32_t b0, uint32_t b1) {
    asm volatile("mma.sync.aligned.m16n8k16.row.col.f32.f16.f16.f32 "
        "{%0,%1,%2,%3}, {%4,%5,%6,%7}, {%8,%9}, {%0,%1,%2,%3};"
        : "+f"(c[0]), "+f"(c[1]), "+f"(c[2]), "+f"(c[3])
        : "r"(a[0]), "r"(a[1]), "r"(a[2]), "r"(a[3]), "r"(b0), "r"(b1));
}
__device__ __forceinline__ void hsplit(float v, __half& h1, __half& h2) {
    h1 = __float2half_rn(v);
    h2 = __float2half_rn(v - __half2float(h1));
}

// merged prep: zero stats + pad x (b-major) + split W0 + copy b0
__global__ void prep_all_kernel(const float* __restrict__ x,
                                const float* __restrict__ W0,
                                const float* __restrict__ b0) {
    int idx = blockIdx.x * blockDim.x + threadIdx.x;
    if (idx < LL * HH) { g_sum[idx] = 0.f; g_sumsq[idx] = 0.f; }
    if (idx < HH) g_beff[idx] = b0[idx];
    if (idx < HH * K0P) {
        int n = idx >> 7, k = idx & 127;
        float v = (k < J3) ? W0[n * J3 + k] : 0.f;
        __half h1, h2; hsplit(v, h1, h2);
        g_B1[idx] = h1; g_B2[idx] = h2;
    }
    if (idx < MM * K0P) {
        int k = idx & 127;
        int bt = idx >> 7;          // b*TT + t
        int b = bt >> 9, t = bt & (TT - 1);
        float v = (k < J3) ? x[(size_t)(t * BB + b) * J3 + k] : 0.f;
        g_Aping[idx] = __float2half_rn(v);
    }
}

__global__ void scale_shift_kernel(const float* __restrict__ sum,
                                   const float* __restrict__ sumsq,
                                   const float* __restrict__ gamma,
                                   const float* __restrict__ beta) {
    int h = blockIdx.x * blockDim.x + threadIdx.x;
    if (h >= HH) return;
    const float inv = 1.0f / (float)(TT * BB);
    float mean = sum[h] * inv;
    float var  = sumsq[h] * inv - mean * mean;
    float sc   = gamma[h] * rsqrtf(var + EPSBN);
    g_scale[h] = sc;
    g_shift[h] = beta[h] - mean * sc;
}

// one block per output row h: BN affine in smem, fold into W row + bias (shuffle reduce)
__global__ __launch_bounds__(HH) void fold_all_kernel(
    const float* __restrict__ W, const float* __restrict__ bh,
    const float* __restrict__ sum, const float* __restrict__ sumsq,
    const float* __restrict__ gamma, const float* __restrict__ beta) {
    __shared__ float s_scale[HH], s_shift[HH], s_warp[16];
    const int t = threadIdx.x;
    {
        const float inv = 1.0f / (float)(TT * BB);
        float mean = sum[t] * inv;
        float var  = sumsq[t] * inv - mean * mean;
        float sc   = gamma[t] * rsqrtf(var + EPSBN);
        s_scale[t] = sc;
        s_shift[t] = beta[t] - mean * sc;
    }
    __syncthreads();
    const int h = blockIdx.x;
    float w = W[h * HH + t];
    float v = w * s_scale[t];
    __half h1, h2; hsplit(v, h1, h2);
    g_B1[h * HH + t] = h1;
    g_B2[h * HH + t] = h2;
    float r = w * s_shift[t];
#pragma unroll
    for (int o = 16; o > 0; o >>= 1) r += __shfl_down_sync(0xFFFFFFFFu, r, o);
    if ((t & 31) == 0) s_warp[t >> 5] = r;
    __syncthreads();
    if (t < 32) {
        float x2 = (t < 16) ? s_warp[t] : 0.f;
#pragma unroll
        for (int o = 8; o > 0; o >>= 1) x2 += __shfl_down_sync(0xFFFFFFFFu, x2, o);
        if (t == 0) g_beff[h] = bh[h] + x2;
    }
}

// Fused layer: per CTA (n-tile of 64, b): 4 t-chunks: GEMM 128x64 -> smem -> scan
// SPLIT_B: 2-pass (B1+B2) high precision; else single-pass fp16 B1.
template <bool WRITE_NEXT, bool SPLIT_B>
__global__ __launch_bounds__(GT, 3) void layer_fused(
    const __half* __restrict__ A,
    const __half* __restrict__ B1, const __half* __restrict__ B2,
    const float* __restrict__ bias, const float* __restrict__ u,
    __half* __restrict__ Anext, float* __restrict__ hlast,
    float* __restrict__ gsum, float* __restrict__ gsumsq, int K) {
    extern __shared__ __align__(128) char smem[];
    const uint32_t sb = smem_u32(smem);
    float* scanbuf = (float*)(smem + STAGE_BYTES);    // overlays stages 1-3
    const int tid = threadIdx.x, wid = tid >> 5, lane = tid & 31;
    const int n0 = blockIdx.x * BN;
    const int b  = blockIdx.y;
    const int NC = K / BK;
    const int wm = wid & 1;        // 2 m-warps -> 64 t-rows each
    const int wn = wid >> 1;       // 2 n-warps -> 32 h-cols each
    const __half* Ab = A + (size_t)b * TT * K;        // contiguous [TT x K] block

    float s_state = 0.f, l_sum = 0.f, l_sq = 0.f, uu = 0.f, bb = 0.f;
    if (tid < BN) { uu = u[n0 + tid]; bb = bias[n0 + tid]; }

    auto load_stage = [&](int tchunk, int c, int sloti) {
        const uint32_t st = sb + sloti * STAGE_BYTES;
        const int k0 = c * BK;
        // SPLIT_B: 1024 cp16 (A 512, B1 256, B2 256); else 768 (A 512, B1 256)
        const int NI = SPLIT_B ? 8 : 6;
#pragma unroll
        for (int i = 0; i < NI; i++) {
            int g = i * GT + tid;
            const __half* src;
            uint32_t dst;
            if (g < 512) {
                int row = g >> 2, ch = g & 3;
                src = Ab + ((size_t)(tchunk * 128 + row) * K + k0 + ch * 8);
                dst = st + OFF_SA + swz64((uint32_t)(row * 64 + ch * 16));
            } else {
                int gg = g - 512;
                int arr = gg >> 8;           // 0:B1 1:B2
                int rem = gg & 255;
                int row = rem >> 2, ch = rem & 3;
                src = (arr ? B2 : B1) + ((size_t)(n0 + row) * K + k0 + ch * 8);
                dst = st + (arr ? OFF_SB2 : OFF_SB1) + swz64((uint32_t)(row * 64 + ch * 16));
            }
            cp16(dst, src);
        }
        cp_commit();
    };

    for (int tc = 0; tc < 4; tc++) {
        float acc[4][4][4];
#pragma unroll
        for (int i = 0; i < 4; i++)
#pragma unroll
            for (int j = 0; j < 4; j++)
#pragma unroll
                for (int q = 0; q < 4; q++) acc[i][j][q] = 0.f;

        // prologue: stage0 of this chunk issued before the previous dump+scan (except tc==0)
        if (tc == 0) load_stage(0, 0, 0);
        load_stage(tc, 1, 1);
        load_stage(tc, 2, 2);

        for (int c = 0; c < NC; c++) {
            cp_wait<2>();            // own groups for stage c done
            __syncthreads();         // cross-warp visibility + slot (c+3)&3 free
            if (c + 3 < NC) load_stage(tc, c + 3, (c + 3) & 3);
            else cp_commit();

            const uint32_t st = sb + (c & 3) * STAGE_BYTES;
#pragma unroll
            for (int ks = 0; ks < 2; ks++) {
                const uint32_t cb = ks * 32 + (lane >> 4) * 16;
                uint32_t af[4][4];
#pragma unroll
                for (int mi = 0; mi < 4; mi++) {
                    uint32_t row = wm * 64 + mi * 16 + (lane & 15);
                    uint32_t off = swz64(row * 64 + cb);
                    ldm_x4(af[mi][0], af[mi][1], af[mi][2], af[mi][3], st + OFF_SA + off);
                }
                uint32_t b1f[4][2], b2f[4][2];
#pragma unroll
                for (int ni = 0; ni < 2; ni++) {
                    uint32_t row = wn * 32 + ni * 16 + (lane & 15);
                    uint32_t off = swz64(row * 64 + cb);
                    uint32_t r0, r1, r2, r3;
                    ldm_x4(r0, r1, r2, r3, st + OFF_SB1 + off);
                    b1f[2*ni][0] = r0; b1f[2*ni][1] = r2;
                    b1f[2*ni+1][0] = r1; b1f[2*ni+1][1] = r3;
                    if (SPLIT_B) {
                        ldm_x4(r0, r1, r2, r3, st + OFF_SB2 + off);
                        b2f[2*ni][0] = r0; b2f[2*ni][1] = r2;
                        b2f[2*ni+1][0] = r1; b2f[2*ni+1][1] = r3;
                    }
                }
#pragma unroll
                for (int mi = 0; mi < 4; mi++)
#pragma unroll
                    for (int nf = 0; nf < 4; nf++)
                        mma_f16(acc[mi][nf], af[mi], b1f[nf][0], b1f[nf][1]);
                if (SPLIT_B) {
#pragma unroll
                    for (int mi = 0; mi < 4; mi++)
#pragma unroll
                        for (int nf = 0; nf < 4; nf++)
                            mma_f16(acc[mi][nf], af[mi], b2f[nf][0], b2f[nf][1]);
                }
            }
        }

        cp_wait<0>();
        __syncthreads();

        // issue next chunk's stage-0 load NOW (slot 0 free, disjoint from scanbuf):
        // it overlaps the accumulator dump AND the scan below.
        if (tc < 3) load_stage(tc + 1, 0, 0);

        // dump accumulators: scanbuf[t_local][h_local] (stages 1-3 region)
        {
            const int group = lane >> 2, tid4 = lane & 3;
#pragma unroll
            for (int nf = 0; nf < 4; nf++) {
                int hc = wn * 32 + nf * 8 + tid4 * 2;
#pragma unroll
                for (int mi = 0; mi < 4; mi++) {
                    int tr = wm * 64 + mi * 16 + group;
                    float2 v0 = { acc[mi][nf][0], acc[mi][nf][1] };
                    float2 v1 = { acc[mi][nf][2], acc[mi][nf][3] };
                    *(float2*)&scanbuf[tr * SCAN_STRIDE + hc] = v0;
                    *(float2*)&scanbuf[(tr + 8) * SCAN_STRIDE + hc] = v1;
                }
            }
        }
        __syncthreads();

        // scan this chunk: threads 0..63, one h-col each; writes b-major
        if (tid < BN) {
#pragma unroll 1
            for (int t0 = 0; t0 < 128; t0 += 8) {
                float v[8];
#pragma unroll
                for (int j = 0; j < 8; j++)
                    v[j] = scanbuf[(t0 + j) * SCAN_STRIDE + tid] + bb;
#pragma unroll
                for (int j = 0; j < 8; j++) {
                    s_state = fmaxf(fmaf(uu, s_state, v[j]), 0.f);
                    if (WRITE_NEXT) {
                        size_t m = (size_t)b * TT + (tc * 128 + t0 + j);
                        Anext[m * HH + n0 + tid] = __float2half_rn(s_state);
                    }
                    l_sum += s_state;
                    l_sq = fmaf(s_state, s_state, l_sq);
                }
            }
        }
        __syncthreads();
    }

    if (tid < BN) {
        if (!WRITE_NEXT) hlast[(size_t)b * HH + n0 + tid] = s_state;
        atomicAdd(&gsum[n0 + tid], l_sum);
        atomicAdd(&gsumsq[n0 + tid], l_sq);
    }
}

__global__ void final_kernel(const float* __restrict__ hl,
                             const float* __restrict__ Wout,
                             const float* __restrict__ bout,
                             float* __restrict__ out) {
    __shared__ float sh[HH];
    int b = blockIdx.x;
    for (int h = threadIdx.x; h < HH; h += blockDim.x)
        sh[h] = fmaf(hl[b * HH + h], g_scale[h], g_shift[h]);
    __syncthreads();
    int c = threadIdx.x;
    if (c < CC) {
        float acc = bout[c];
#pragma unroll 8
        for (int h = 0; h < HH; h++)
            acc = fmaf(sh[h], Wout[c * HH + h], acc);
        out[b * CC + c] = acc;
    }
}

extern "C" void kernel_launch(void* const* d_in, const int* in_sizes, int n_in,
                              void* d_out, int out_size) {
    const float* x     = (const float*)d_in[0];
    const float* W0    = (const float*)d_in[1];
    const float* b0    = (const float*)d_in[2];
    const float* Wh    = (const float*)d_in[3];
    const float* bh    = (const float*)d_in[4];
    const float* u     = (const float*)d_in[5];
    const float* gamma = (const float*)d_in[6];
    const float* beta  = (const float*)d_in[7];
    const float* Wout  = (const float*)d_in[8];
    const float* bout  = (const float*)d_in[9];
    float* out = (float*)d_out;

    float *beff, *sum, *sumsq, *hlast;
    __half *Aping, *Apong, *B1, *B2;
    cudaGetSymbolAddress((void**)&Aping, g_Aping);
    cudaGetSymbolAddress((void**)&Apong, g_Apong);
    cudaGetSymbolAddress((void**)&B1, g_B1);
    cudaGetSymbolAddress((void**)&B2, g_B2);
    cudaGetSymbolAddress((void**)&beff, g_beff);
    cudaGetSymbolAddress((void**)&sum, g_sum);
    cudaGetSymbolAddress((void**)&sumsq, g_sumsq);
    cudaGetSymbolAddress((void**)&hlast, g_hlast);

    cudaFuncSetAttribute(layer_fused<true, true>, cudaFuncAttributeMaxDynamicSharedMemorySize, FSMEM);
    cudaFuncSetAttribute(layer_fused<true, false>, cudaFuncAttributeMaxDynamicSharedMemorySize, FSMEM);
    cudaFuncSetAttribute(layer_fused<false, true>, cudaFuncAttributeMaxDynamicSharedMemorySize, FSMEM);

    // launch order: 0:prep_all 1:layer0 2:fold 3:layer1 <- ncu captures #3
    prep_all_kernel<<<(MM * K0P + 255) / 256, 256>>>(x, W0, b0);

    dim3 fgrid(NN / BN, BB);

    // layer 0: K=128, split-B
    layer_fused<true, true><<<fgrid, GT, FSMEM>>>(Aping, B1, B2, beff, u, Apong,
                                                  nullptr, sum, sumsq, K0P);
    __half* cur = Apong;
    __half* nxt = Aping;

    for (int l = 1; l < LL; l++) {
        const float* Wl  = Wh + (size_t)(l - 1) * HH * HH;
        const float* bhl = bh + (size_t)(l - 1) * HH;
        fold_all_kernel<<<HH, HH>>>(Wl, bhl, sum + (l - 1) * HH, sumsq + (l - 1) * HH,
                                    gamma + (l - 1) * HH, beta + (l - 1) * HH);
        if (l == 2) {
            // single-B layer (calibrated error budget: +0.402e-3 in quadrature)
            layer_fused<true, false><<<fgrid, GT, FSMEM>>>(cur, B1, B2, beff, u + l * HH, nxt,
                                                           nullptr, sum + l * HH, sumsq + l * HH, HH);
            __half* t = cur; cur = nxt; nxt = t;
        } else if (l < LL - 1) {
            layer_fused<true, true><<<fgrid, GT, FSMEM>>>(cur, B1, B2, beff, u + l * HH, nxt,
                                                          nullptr, sum + l * HH, sumsq + l * HH, HH);
            __half* t = cur; cur = nxt; nxt = t;
        } else {
            layer_fused<false, true><<<fgrid, GT, FSMEM>>>(cur, B1, B2, beff, u + l * HH, nullptr,
                                                           hlast, sum + l * HH, sumsq + l * HH, HH);
        }
    }

    scale_shift_kernel<<<2, 256>>>(sum + (LL - 1) * HH, sumsq + (LL - 1) * HH,
                                   gamma + (LL - 1) * HH, beta + (LL - 1) * HH);
    final_kernel<<<BB, 64>>>(hlast, Wout, bout, out);
}

// round 16
// speedup vs baseline: 1.3261x; 1.0735x over previous
#include <cuda_runtime.h>
#include <cuda_fp16.h>
#include <cstdint>

#define TT 512
#define BB 128
#define HH 512
#define LL 6
#define CC 60
#define J3 75
#define K0P 128
#define BH (BB*HH)
#define MM (TT*BB)
#define NN 512
#define EPSBN 1e-5f

// fused layer: per CTA: one b, 64 h-cols, 4 t-chunks of 128
// 128 threads = 4 warps in 2x2 grid of 64x32 warp tiles
#define BM 128
#define BN 64
#define BK 32
#define GT 128
#define NSTAGE 4
#define STAGE_BYTES 16384   // A(8K)+B1(4K)+B2(4K)
#define OFF_SA  0
#define OFF_SB1 8192
#define OFF_SB2 12288
#define SCAN_STRIDE 72      // floats per row (64 + pad 8)
#define FSMEM (NSTAGE*STAGE_BYTES)   // 65536; scanbuf (36864) overlays stages 1-3

// activations stored b-major: A[(b*TT + t)*K + k]
__device__ __half g_Aping[(size_t)MM * HH];
__device__ __half g_Apong[(size_t)MM * HH];
__device__ __half g_B1[HH * HH];
__device__ __half g_B2[HH * HH];
__device__ float g_beff[HH];
__device__ float g_scale[HH];
__device__ float g_shift[HH];
__device__ float g_sum[LL * HH];
__device__ float g_sumsq[LL * HH];
__device__ float g_hlast[BH];

__device__ __forceinline__ uint32_t smem_u32(const void* p) {
    uint32_t a;
    asm("{ .reg .u64 t; cvta.to.shared.u64 t, %1; cvt.u32.u64 %0, t; }" : "=r"(a) : "l"(p));
    return a;
}
__device__ __forceinline__ uint32_t swz64(uint32_t off) { return off ^ ((off >> 3) & 0x30); }
__device__ __forceinline__ void cp16(uint32_t dst, const void* src) {
    asm volatile("cp.async.cg.shared.global [%0], [%1], 16;\n" :: "r"(dst), "l"(src));
}
__device__ __forceinline__ void cp_commit() { asm volatile("cp.async.commit_group;\n" ::: "memory"); }
template <int N> __device__ __forceinline__ void cp_wait() {
    asm volatile("cp.async.wait_group %0;\n" :: "n"(N) : "memory");
}
__device__ __forceinline__ void ldm_x4(uint32_t& r0, uint32_t& r1, uint32_t& r2, uint32_t& r3,
                                       uint32_t addr) {
    asm volatile("ldmatrix.sync.aligned.m8n8.x4.shared.b16 {%0,%1,%2,%3}, [%4];"
        : "=r"(r0), "=r"(r1), "=r"(r2), "=r"(r3) : "r"(addr));
}
__device__ __forceinline__ void mma_f16(float* c, const uint32_t* a, uint32_t b0, uint32_t b1) {
    asm volatile("mma.sync.aligned.m16n8k16.row.col.f32.f16.f16.f32 "
        "{%0,%1,%2,%3}, {%4,%5,%6,%7}, {%8,%9}, {%0,%1,%2,%3};"
        : "+f"(c[0]), "+f"(c[1]), "+f"(c[2]), "+f"(c[3])
        : "r"(a[0]), "r"(a[1]), "r"(a[2]), "r"(a[3]), "r"(b0), "r"(b1));
}
__device__ __forceinline__ void hsplit(float v, __half& h1, __half& h2) {
    h1 = __float2half_rn(v);
    h2 = __float2half_rn(v - __half2float(h1));
}

// merged prep: zero stats + pad x (b-major) + split W0 + copy b0
__global__ void prep_all_kernel(const float* __restrict__ x,
                                const float* __restrict__ W0,
                                const float* __restrict__ b0) {
    int idx = blockIdx.x * blockDim.x + threadIdx.x;
    if (idx < LL * HH) { g_sum[idx] = 0.f; g_sumsq[idx] = 0.f; }
    if (idx < HH) g_beff[idx] = b0[idx];
    if (idx < HH * K0P) {
        int n = idx >> 7, k = idx & 127;
        float v = (k < J3) ? W0[n * J3 + k] : 0.f;
        __half h1, h2; hsplit(v, h1, h2);
        g_B1[idx] = h1; g_B2[idx] = h2;
    }
    if (idx < MM * K0P) {
        int k = idx & 127;
        int bt = idx >> 7;          // b*TT + t
        int b = bt >> 9, t = bt & (TT - 1);
        float v = (k < J3) ? x[(size_t)(t * BB + b) * J3 + k] : 0.f;
        g_Aping[idx] = __float2half_rn(v);
    }
}

__global__ void scale_shift_kernel(const float* __restrict__ sum,
                                   const float* __restrict__ sumsq,
                                   const float* __restrict__ gamma,
                                   const float* __restrict__ beta) {
    int h = blockIdx.x * blockDim.x + threadIdx.x;
    if (h >= HH) return;
    const float inv = 1.0f / (float)(TT * BB);
    float mean = sum[h] * inv;
    float var  = sumsq[h] * inv - mean * mean;
    float sc   = gamma[h] * rsqrtf(var + EPSBN);
    g_scale[h] = sc;
    g_shift[h] = beta[h] - mean * sc;
}

// one block per output row h: BN affine in smem, fold into W row + bias (shuffle reduce)
__global__ __launch_bounds__(HH) void fold_all_kernel(
    const float* __restrict__ W, const float* __restrict__ bh,
    const float* __restrict__ sum, const float* __restrict__ sumsq,
    const float* __restrict__ gamma, const float* __restrict__ beta) {
    __shared__ float s_scale[HH], s_shift[HH], s_warp[16];
    const int t = threadIdx.x;
    {
        const float inv = 1.0f / (float)(TT * BB);
        float mean = sum[t] * inv;
        float var  = sumsq[t] * inv - mean * mean;
        float sc   = gamma[t] * rsqrtf(var + EPSBN);
        s_scale[t] = sc;
        s_shift[t] = beta[t] - mean * sc;
    }
    __syncthreads();
    const int h = blockIdx.x;
    float w = W[h * HH + t];
    float v = w * s_scale[t];
    __half h1, h2; hsplit(v, h1, h2);
    g_B1[h * HH + t] = h1;
    g_B2[h * HH + t] = h2;
    float r = w * s_shift[t];
#pragma unroll
    for (int o = 16; o > 0; o >>= 1) r += __shfl_down_sync(0xFFFFFFFFu, r, o);
    if ((t & 31) == 0) s_warp[t >> 5] = r;
    __syncthreads();
    if (t < 32) {
        float x2 = (t < 16) ? s_warp[t] : 0.f;
#pragma unroll
        for (int o = 8; o > 0; o >>= 1) x2 += __shfl_down_sync(0xFFFFFFFFu, x2, o);
        if (t == 0) g_beff[h] = bh[h] + x2;
    }
}

// Fused layer: per CTA (n-tile of 64, b): 4 t-chunks: GEMM 128x64 -> smem -> scan
// SPLIT_B: 2-pass (B1+B2) high precision; else single-pass fp16 B1.
template <bool WRITE_NEXT, bool SPLIT_B>
__global__ __launch_bounds__(GT, 3) void layer_fused(
    const __half* __restrict__ A,
    const __half* __restrict__ B1, const __half* __restrict__ B2,
    const float* __restrict__ bias, const float* __restrict__ u,
    __half* __restrict__ Anext, float* __restrict__ hlast,
    float* __restrict__ gsum, float* __restrict__ gsumsq, int K) {
    extern __shared__ __align__(128) char smem[];
    const uint32_t sb = smem_u32(smem);
    float* scanbuf = (float*)(smem + STAGE_BYTES);    // overlays stages 1-3
    const int tid = threadIdx.x, wid = tid >> 5, lane = tid & 31;
    const int n0 = blockIdx.x * BN;
    const int b  = blockIdx.y;
    const int NC = K / BK;
    const int wm = wid & 1;        // 2 m-warps -> 64 t-rows each
    const int wn = wid >> 1;       // 2 n-warps -> 32 h-cols each
    const __half* Ab = A + (size_t)b * TT * K;        // contiguous [TT x K] block

    float s_state = 0.f, l_sum = 0.f, l_sq = 0.f, uu = 0.f, bb = 0.f;
    if (tid < BN) { uu = u[n0 + tid]; bb = bias[n0 + tid]; }

    auto load_stage = [&](int tchunk, int c, int sloti) {
        const uint32_t st = sb + sloti * STAGE_BYTES;
        const int k0 = c * BK;
        // SPLIT_B: 1024 cp16 (A 512, B1 256, B2 256); else 768 (A 512, B1 256)
        const int NI = SPLIT_B ? 8 : 6;
#pragma unroll
        for (int i = 0; i < NI; i++) {
            int g = i * GT + tid;
            const __half* src;
            uint32_t dst;
            if (g < 512) {
                int row = g >> 2, ch = g & 3;
                src = Ab + ((size_t)(tchunk * 128 + row) * K + k0 + ch * 8);
                dst = st + OFF_SA + swz64((uint32_t)(row * 64 + ch * 16));
            } else {
                int gg = g - 512;
                int arr = gg >> 8;           // 0:B1 1:B2
                int rem = gg & 255;
                int row = rem >> 2, ch = rem & 3;
                src = (arr ? B2 : B1) + ((size_t)(n0 + row) * K + k0 + ch * 8);
                dst = st + (arr ? OFF_SB2 : OFF_SB1) + swz64((uint32_t)(row * 64 + ch * 16));
            }
            cp16(dst, src);
        }
        cp_commit();
    };

    for (int tc = 0; tc < 4; tc++) {
        float acc[4][4][4];
#pragma unroll
        for (int i = 0; i < 4; i++)
#pragma unroll
            for (int j = 0; j < 4; j++)
#pragma unroll
                for (int q = 0; q < 4; q++) acc[i][j][q] = 0.f;

        // prologue: stage0 of this chunk issued before the previous dump+scan (except tc==0)
        if (tc == 0) load_stage(0, 0, 0);
        load_stage(tc, 1, 1);
        load_stage(tc, 2, 2);

        for (int c = 0; c < NC; c++) {
            cp_wait<2>();            // own groups for stage c done
            __syncthreads();         // cross-warp visibility + slot (c+3)&3 free
            if (c + 3 < NC) load_stage(tc, c + 3, (c + 3) & 3);
            else cp_commit();

            const uint32_t st = sb + (c & 3) * STAGE_BYTES;
#pragma unroll
            for (int ks = 0; ks < 2; ks++) {
                const uint32_t cb = ks * 32 + (lane >> 4) * 16;
                uint32_t af[4][4];
#pragma unroll
                for (int mi = 0; mi < 4; mi++) {
                    uint32_t row = wm * 64 + mi * 16 + (lane & 15);
                    uint32_t off = swz64(row * 64 + cb);
                    ldm_x4(af[mi][0], af[mi][1], af[mi][2], af[mi][3], st + OFF_SA + off);
                }
                uint32_t b1f[4][2], b2f[4][2];
#pragma unroll
                for (int ni = 0; ni < 2; ni++) {
                    uint32_t row = wn * 32 + ni * 16 + (lane & 15);
                    uint32_t off = swz64(row * 64 + cb);
                    uint32_t r0, r1, r2, r3;
                    ldm_x4(r0, r1, r2, r3, st + OFF_SB1 + off);
                    b1f[2*ni][0] = r0; b1f[2*ni][1] = r2;
                    b1f[2*ni+1][0] = r1; b1f[2*ni+1][1] = r3;
                    if (SPLIT_B) {
                        ldm_x4(r0, r1, r2, r3, st + OFF_SB2 + off);
                        b2f[2*ni][0] = r0; b2f[2*ni][1] = r2;
                        b2f[2*ni+1][0] = r1; b2f[2*ni+1][1] = r3;
                    }
                }
#pragma unroll
                for (int mi = 0; mi < 4; mi++)
#pragma unroll
                    for (int nf = 0; nf < 4; nf++)
                        mma_f16(acc[mi][nf], af[mi], b1f[nf][0], b1f[nf][1]);
                if (SPLIT_B) {
#pragma unroll
                    for (int mi = 0; mi < 4; mi++)
#pragma unroll
                        for (int nf = 0; nf < 4; nf++)
                            mma_f16(acc[mi][nf], af[mi], b2f[nf][0], b2f[nf][1]);
                }
            }
        }

        cp_wait<0>();
        __syncthreads();

        // issue next chunk's stage-0 load NOW (slot 0 free, disjoint from scanbuf):
        // it overlaps the accumulator dump AND the scan below.
        if (tc < 3) load_stage(tc + 1, 0, 0);

        // dump accumulators: scanbuf[t_local][h_local] (stages 1-3 region)
        {
            const int group = lane >> 2, tid4 = lane & 3;
#pragma unroll
            for (int nf = 0; nf < 4; nf++) {
                int hc = wn * 32 + nf * 8 + tid4 * 2;
#pragma unroll
                for (int mi = 0; mi < 4; mi++) {
                    int tr = wm * 64 + mi * 16 + group;
                    float2 v0 = { acc[mi][nf][0], acc[mi][nf][1] };
                    float2 v1 = { acc[mi][nf][2], acc[mi][nf][3] };
                    *(float2*)&scanbuf[tr * SCAN_STRIDE + hc] = v0;
                    *(float2*)&scanbuf[(tr + 8) * SCAN_STRIDE + hc] = v1;
                }
            }
        }
        __syncthreads();

        // scan this chunk: threads 0..63, one h-col each; writes b-major
        if (tid < BN) {
#pragma unroll 1
            for (int t0 = 0; t0 < 128; t0 += 8) {
                float v[8];
#pragma unroll
                for (int j = 0; j < 8; j++)
                    v[j] = scanbuf[(t0 + j) * SCAN_STRIDE + tid] + bb;
#pragma unroll
                for (int j = 0; j < 8; j++) {
                    s_state = fmaxf(fmaf(uu, s_state, v[j]), 0.f);
                    if (WRITE_NEXT) {
                        size_t m = (size_t)b * TT + (tc * 128 + t0 + j);
                        Anext[m * HH + n0 + tid] = __float2half_rn(s_state);
                    }
                    l_sum += s_state;
                    l_sq = fmaf(s_state, s_state, l_sq);
                }
            }
        }
        __syncthreads();
    }

    if (tid < BN) {
        if (!WRITE_NEXT) hlast[(size_t)b * HH + n0 + tid] = s_state;
        atomicAdd(&gsum[n0 + tid], l_sum);
        atomicAdd(&gsumsq[n0 + tid], l_sq);
    }
}

__global__ void final_kernel(const float* __restrict__ hl,
                             const float* __restrict__ Wout,
                             const float* __restrict__ bout,
                             float* __restrict__ out) {
    __shared__ float sh[HH];
    int b = blockIdx.x;
    for (int h = threadIdx.x; h < HH; h += blockDim.x)
        sh[h] = fmaf(hl[b * HH + h], g_scale[h], g_shift[h]);
    __syncthreads();
    int c = threadIdx.x;
    if (c < CC) {
        float acc = bout[c];
#pragma unroll 8
        for (int h = 0; h < HH; h++)
            acc = fmaf(sh[h], Wout[c * HH + h], acc);
        out[b * CC + c] = acc;
    }
}

extern "C" void kernel_launch(void* const* d_in, const int* in_sizes, int n_in,
                              void* d_out, int out_size) {
    const float* x     = (const float*)d_in[0];
    const float* W0    = (const float*)d_in[1];
    const float* b0    = (const float*)d_in[2];
    const float* Wh    = (const float*)d_in[3];
    const float* bh    = (const float*)d_in[4];
    const float* u     = (const float*)d_in[5];
    const float* gamma = (const float*)d_in[6];
    const float* beta  = (const float*)d_in[7];
    const float* Wout  = (const float*)d_in[8];
    const float* bout  = (const float*)d_in[9];
    float* out = (float*)d_out;

    float *beff, *sum, *sumsq, *hlast;
    __half *Aping, *Apong, *B1, *B2;
    cudaGetSymbolAddress((void**)&Aping, g_Aping);
    cudaGetSymbolAddress((void**)&Apong, g_Apong);
    cudaGetSymbolAddress((void**)&B1, g_B1);
    cudaGetSymbolAddress((void**)&B2, g_B2);
    cudaGetSymbolAddress((void**)&beff, g_beff);
    cudaGetSymbolAddress((void**)&sum, g_sum);
    cudaGetSymbolAddress((void**)&sumsq, g_sumsq);
    cudaGetSymbolAddress((void**)&hlast, g_hlast);

    cudaFuncSetAttribute(layer_fused<true, true>, cudaFuncAttributeMaxDynamicSharedMemorySize, FSMEM);
    cudaFuncSetAttribute(layer_fused<true, false>, cudaFuncAttributeMaxDynamicSharedMemorySize, FSMEM);
    cudaFuncSetAttribute(layer_fused<false, true>, cudaFuncAttributeMaxDynamicSharedMemorySize, FSMEM);

    // launch order: 0:prep_all 1:layer0 2:fold 3:layer1 <- ncu captures #3
    prep_all_kernel<<<(MM * K0P + 255) / 256, 256>>>(x, W0, b0);

    dim3 fgrid(NN / BN, BB);

    // layer 0: K=128, split-B
    layer_fused<true, true><<<fgrid, GT, FSMEM>>>(Aping, B1, B2, beff, u, Apong,
                                                  nullptr, sum, sumsq, K0P);
    __half* cur = Apong;
    __half* nxt = Aping;

    for (int l = 1; l < LL; l++) {
        const float* Wl  = Wh + (size_t)(l - 1) * HH * HH;
        const float* bhl = bh + (size_t)(l - 1) * HH;
        fold_all_kernel<<<HH, HH>>>(Wl, bhl, sum + (l - 1) * HH, sumsq + (l - 1) * HH,
                                    gamma + (l - 1) * HH, beta + (l - 1) * HH);
        if (l == 2 || l == 3) {
            // single-B layers (calibrated: +0.396e-3 each in quadrature -> ~0.888e-3 total)
            layer_fused<true, false><<<fgrid, GT, FSMEM>>>(cur, B1, B2, beff, u + l * HH, nxt,
                                                           nullptr, sum + l * HH, sumsq + l * HH, HH);
            __half* t = cur; cur = nxt; nxt = t;
        } else if (l < LL - 1) {
            layer_fused<true, true><<<fgrid, GT, FSMEM>>>(cur, B1, B2, beff, u + l * HH, nxt,
                                                          nullptr, sum + l * HH, sumsq + l * HH, HH);
            __half* t = cur; cur = nxt; nxt = t;
        } else {
            layer_fused<false, true><<<fgrid, GT, FSMEM>>>(cur, B1, B2, beff, u + l * HH, nullptr,
                                                           hlast, sum + l * HH, sumsq + l * HH, HH);
        }
    }

    scale_shift_kernel<<<2, 256>>>(sum + (LL - 1) * HH, sumsq + (LL - 1) * HH,
                                   gamma + (LL - 1) * HH, beta + (LL - 1) * HH);
    final_kernel<<<BB, 64>>>(hlast, Wout, bout, out);
}